// round 2
// baseline (speedup 1.0000x reference)
#include <cuda_runtime.h>
#include <cuda_bf16.h>

#define VOCAB 30000
#define EMB 128
#define ENC 128
#define BS 256
#define NNODES 1023

// Precomputed P[t][o] = dot(emb[t,:], W_c[o,:]) + b_c[o]   (15.36 MB scratch)
__device__ float g_P[VOCAB * ENC];

// Packed f32x2 FMA (Blackwell FFMA2) — PTX-only path.
__device__ __forceinline__ unsigned long long fma2(unsigned long long a,
                                                   unsigned long long b,
                                                   unsigned long long c) {
    unsigned long long d;
    asm("fma.rn.f32x2 %0, %1, %2, %3;" : "=l"(d) : "l"(a), "l"(b), "l"(c));
    return d;
}

// ---------------------------------------------------------------------------
// Kernel A: P = emb @ W_c^T + b_c
//   256 threads/CTA, 32 emb rows x 128 out cols; thread tile 2 rows x 8 cols.
//   Per k: 2x LDS.64 (prepacked {a,a}) + 2x LDS.128 (w pairs) + 8 FFMA2.
//   smem = 67584 (W^T, stride 132) + 32768 (A packed) = 100352 B -> 2 CTAs/SM.
// ---------------------------------------------------------------------------
#define A_ROWS 32
#define W_STRIDE 132

__global__ void __launch_bounds__(256) pmat_kernel(const float* __restrict__ emb,
                                                   const float* __restrict__ Wc,
                                                   const float* __restrict__ bc) {
    extern __shared__ char smem_raw[];
    float* sW = (float*)smem_raw;                                              // 128*132*4
    unsigned long long* sA = (unsigned long long*)(smem_raw + 128 * W_STRIDE * 4); // 32*128*8

    const int tid = threadIdx.x;
    const int row0 = blockIdx.x * A_ROWS;

    // W transposed into smem: sW[k*132 + o] = Wc[o*128 + k] (coalesced reads).
    #pragma unroll 8
    for (int i = tid; i < 128 * 128; i += 256) {
        int o = i >> 7, k = i & 127;
        sW[k * W_STRIDE + o] = Wc[i];
    }
    // A tile pre-packed as {a,a} f32x2; zero-fill past VOCAB.
    #pragma unroll 4
    for (int i = tid; i < A_ROWS * 128; i += 256) {
        int r = i >> 7;
        float a = 0.0f;
        if (row0 + r < VOCAB) a = emb[(size_t)row0 * 128 + i];
        unsigned au = __float_as_uint(a);
        sA[i] = ((unsigned long long)au << 32) | (unsigned long long)au;
    }
    __syncthreads();

    const int rg = tid >> 4;   // 0..15 : rows rg*2, rg*2+1
    const int cg = tid & 15;   // 0..15 : cols cg*8 .. cg*8+7

    unsigned long long acc0[4], acc1[4];
    #pragma unroll
    for (int j = 0; j < 4; j++) { acc0[j] = 0ull; acc1[j] = 0ull; }

    const unsigned long long* A0 = sA + (rg * 2) * 128;
    const unsigned long long* A1 = A0 + 128;
    const float* Wp = sW + cg * 8;

    #pragma unroll 8
    for (int k = 0; k < 128; k++) {
        ulonglong2 wlo = *(const ulonglong2*)(Wp + k * W_STRIDE);      // w pairs 0,1
        ulonglong2 whi = *(const ulonglong2*)(Wp + k * W_STRIDE + 4);  // w pairs 2,3
        unsigned long long a0 = A0[k];
        unsigned long long a1 = A1[k];
        acc0[0] = fma2(a0, wlo.x, acc0[0]);
        acc0[1] = fma2(a0, wlo.y, acc0[1]);
        acc0[2] = fma2(a0, whi.x, acc0[2]);
        acc0[3] = fma2(a0, whi.y, acc0[3]);
        acc1[0] = fma2(a1, wlo.x, acc1[0]);
        acc1[1] = fma2(a1, wlo.y, acc1[1]);
        acc1[2] = fma2(a1, whi.x, acc1[2]);
        acc1[3] = fma2(a1, whi.y, acc1[3]);
    }

    float4 bv0 = *(const float4*)(bc + cg * 8);
    float4 bv1 = *(const float4*)(bc + cg * 8 + 4);

    #pragma unroll
    for (int r = 0; r < 2; r++) {
        int row = row0 + rg * 2 + r;
        if (row < VOCAB) {
            const unsigned long long* acc = r ? acc1 : acc0;
            float x[8];
            #pragma unroll
            for (int j = 0; j < 4; j++)
                asm("mov.b64 {%0,%1}, %2;" : "=f"(x[2*j]), "=f"(x[2*j+1]) : "l"(acc[j]));
            float4 o0, o1;
            o0.x = x[0] + bv0.x; o0.y = x[1] + bv0.y; o0.z = x[2] + bv0.z; o0.w = x[3] + bv0.w;
            o1.x = x[4] + bv1.x; o1.y = x[5] + bv1.y; o1.z = x[6] + bv1.z; o1.w = x[7] + bv1.w;
            float* dst = g_P + (size_t)row * 128 + cg * 8;
            *(float4*)dst = o0;
            *(float4*)(dst + 4) = o1;
        }
    }
}

// ---------------------------------------------------------------------------
// Kernel B: per (batch, channel-half) CTA: bottom-up subtree sums + max.
//   grid = BS*2, 256 threads. ch = tid&63 (64 channels), grp = tid>>6 (0..3).
//   Tokens staged in smem (kills chained global latency). 28.7 KB smem ->
//   8 CTAs/SM = 64 warps (full occupancy).
// ---------------------------------------------------------------------------
__global__ void __launch_bounds__(256) tree_kernel(const int* __restrict__ tokens,
                                                   float* __restrict__ out) {
    __shared__ int   stok[1024];        //  4 KB
    __shared__ float bufA[64 * 64];     // 16 KB
    __shared__ float bufB[32 * 64];     //  8 KB

    const int bh   = blockIdx.x;
    const int b    = bh >> 1;
    const int chb  = (bh & 1) << 6;     // 0 or 64
    const int tid  = threadIdx.x;
    const int ch   = tid & 63;
    const int grp  = tid >> 6;
    const int* tokrow = tokens + (size_t)b * NNODES;

    // Stage tokens (coalesced, once).
    for (int i = tid; i < NNODES; i += 256) stok[i] = tokrow[i];
    __syncthreads();

    const float* Pc = g_P + chb + ch;   // gather base for this thread's channel
    float maxv = -3.4e38f;

    // ---- fused levels 9..6: 64 subtrees rooted at level-6 nodes q = 63+m ----
    for (int m = grp; m < 64; m += 4) {
        int q = 63 + m;
        int b2 = 2 * q + 1, b4 = 4 * q + 3, b8 = 8 * q + 7;
        float v[15];
        v[0] = __ldg(Pc + (size_t)stok[q] * 128);
        #pragma unroll
        for (int j = 0; j < 2; j++) v[1 + j] = __ldg(Pc + (size_t)stok[b2 + j] * 128);
        #pragma unroll
        for (int j = 0; j < 4; j++) v[3 + j] = __ldg(Pc + (size_t)stok[b4 + j] * 128);
        #pragma unroll
        for (int j = 0; j < 8; j++) v[7 + j] = __ldg(Pc + (size_t)stok[b8 + j] * 128);

        float s8[4];
        #pragma unroll
        for (int j = 0; j < 4; j++) {
            float lft = v[7 + 2 * j], rgt = v[8 + 2 * j];
            maxv = fmaxf(maxv, fmaxf(lft, rgt));
            s8[j] = v[3 + j] + lft + rgt;
            maxv = fmaxf(maxv, s8[j]);
        }
        float s70 = v[1] + s8[0] + s8[1];
        float s71 = v[2] + s8[2] + s8[3];
        maxv = fmaxf(maxv, fmaxf(s70, s71));
        float s6 = v[0] + s70 + s71;
        maxv = fmaxf(maxv, s6);
        bufA[m * 64 + ch] = s6;
    }
    __syncthreads();

    // ---- levels 5..0 via smem ping-pong ----
    for (int i = grp; i < 32; i += 4) {          // l5: A(64)->B(32)
        float v = bufA[(2 * i) * 64 + ch] + bufA[(2 * i + 1) * 64 + ch]
                + __ldg(Pc + (size_t)stok[31 + i] * 128);
        maxv = fmaxf(maxv, v);
        bufB[i * 64 + ch] = v;
    }
    __syncthreads();
    for (int i = grp; i < 16; i += 4) {          // l4: B(32)->A(16)
        float v = bufB[(2 * i) * 64 + ch] + bufB[(2 * i + 1) * 64 + ch]
                + __ldg(Pc + (size_t)stok[15 + i] * 128);
        maxv = fmaxf(maxv, v);
        bufA[i * 64 + ch] = v;
    }
    __syncthreads();
    for (int i = grp; i < 8; i += 4) {           // l3: A(16)->B(8)
        float v = bufA[(2 * i) * 64 + ch] + bufA[(2 * i + 1) * 64 + ch]
                + __ldg(Pc + (size_t)stok[7 + i] * 128);
        maxv = fmaxf(maxv, v);
        bufB[i * 64 + ch] = v;
    }
    __syncthreads();
    {                                            // l2: B(8)->A(4)
        int i = grp;
        float v = bufB[(2 * i) * 64 + ch] + bufB[(2 * i + 1) * 64 + ch]
                + __ldg(Pc + (size_t)stok[3 + i] * 128);
        maxv = fmaxf(maxv, v);
        bufA[i * 64 + ch] = v;
    }
    __syncthreads();
    if (grp < 2) {                               // l1: A(4)->B(2)
        int i = grp;
        float v = bufA[(2 * i) * 64 + ch] + bufA[(2 * i + 1) * 64 + ch]
                + __ldg(Pc + (size_t)stok[1 + i] * 128);
        maxv = fmaxf(maxv, v);
        bufB[i * 64 + ch] = v;
    }
    __syncthreads();
    if (grp == 0) {                              // l0: root
        float v = bufB[ch] + bufB[64 + ch] + __ldg(Pc + (size_t)stok[0] * 128);
        maxv = fmaxf(maxv, v);
    }

    // ---- cross-group max (reuse bufA) ----
    bufA[tid] = maxv;
    __syncthreads();
    if (grp == 0) {
        float m = fmaxf(fmaxf(bufA[ch], bufA[64 + ch]),
                        fmaxf(bufA[128 + ch], bufA[192 + ch]));
        out[(size_t)b * 128 + chb + ch] = m;
    }
}

// ---------------------------------------------------------------------------
// kernel_launch
// ---------------------------------------------------------------------------
extern "C" void kernel_launch(void* const* d_in, const int* in_sizes, int n_in,
                              void* d_out, int out_size) {
    const int*   tokens = (const int*)d_in[0];
    const float* emb    = (const float*)d_in[1];
    const float* Wc     = (const float*)d_in[2];
    const float* bc     = (const float*)d_in[3];
    float*       out    = (float*)d_out;

    const size_t smemA = (size_t)128 * W_STRIDE * 4 + (size_t)A_ROWS * 128 * 8; // 100352
    cudaFuncSetAttribute(pmat_kernel, cudaFuncAttributeMaxDynamicSharedMemorySize, (int)smemA);

    const int gridA = (VOCAB + A_ROWS - 1) / A_ROWS;  // 938
    pmat_kernel<<<gridA, 256, smemA>>>(emb, Wc, bc);
    tree_kernel<<<BS * 2, 256>>>(tokens, out);
}

// round 4
// speedup vs baseline: 3.3779x; 3.3779x over previous
#include <cuda_runtime.h>
#include <cuda_bf16.h>
#include <cstdint>

#define VOCAB 30000
#define EMB 128
#define ENC 128
#define BS 256
#define NNODES 1023

// Precomputed P[t][o] = dot(emb[t,:], W_c[o,:]) + b_c[o]   (15.36 MB scratch)
__device__ float g_P[VOCAB * ENC];

// ---------------------------------------------------------------------------
// Kernel A: P = emb @ W_c^T + b_c via mma.sync m16n8k16 bf16 (HMMA),
// split-precision: emb=eh+el, W=wh+wl, D = eh*wh + eh*wl + el*wh (fp32 acc).
//   CTA: 256 thr (8 warps), tile M=64 x N=128 x K=128.
//   Warp w: rows m0=(w&1)*32 (2 m16 tiles), cols n0=(w>>1)*32 (4 n8 tiles).
//   smem tiles bf16, row stride 136 elems (conflict-free fragment LDS.32).
// ---------------------------------------------------------------------------
#define MT 64
#define SAS 136   // smem row stride in bf16 elements

// D += A(16x16) * B(16x8);  A row-major frag {a0..a3}, B col frag {b0,b1}
#define MMA16816(c, a, b)                                                   \
    asm("mma.sync.aligned.m16n8k16.row.col.f32.bf16.bf16.f32 "              \
        "{%0,%1,%2,%3}, {%4,%5,%6,%7}, {%8,%9}, {%0,%1,%2,%3};"             \
        : "+f"((c)[0]), "+f"((c)[1]), "+f"((c)[2]), "+f"((c)[3])            \
        : "r"((a)[0]), "r"((a)[1]), "r"((a)[2]), "r"((a)[3]),               \
          "r"((b)[0]), "r"((b)[1]))

// split fp32x4 into bf16-hi x4 and bf16-lo x4, store as uint2 at h/l + off
__device__ __forceinline__ void split_store(uint16_t* __restrict__ h,
                                            uint16_t* __restrict__ l,
                                            int off, float4 x) {
    __nv_bfloat162 h01 = __floats2bfloat162_rn(x.x, x.y);
    __nv_bfloat162 h23 = __floats2bfloat162_rn(x.z, x.w);
    __nv_bfloat162 l01 = __floats2bfloat162_rn(x.x - __bfloat162float(h01.x),
                                               x.y - __bfloat162float(h01.y));
    __nv_bfloat162 l23 = __floats2bfloat162_rn(x.z - __bfloat162float(h23.x),
                                               x.w - __bfloat162float(h23.y));
    *(uint2*)(h + off) = make_uint2(*(uint32_t*)&h01, *(uint32_t*)&h23);
    *(uint2*)(l + off) = make_uint2(*(uint32_t*)&l01, *(uint32_t*)&l23);
}

__global__ void __launch_bounds__(256) pmat_kernel(const float* __restrict__ emb,
                                                   const float* __restrict__ Wc,
                                                   const float* __restrict__ bc) {
    extern __shared__ __align__(16) char dsm[];
    uint16_t* sAh = (uint16_t*)dsm;                    // 64*136*2  = 17408 B
    uint16_t* sAl = (uint16_t*)(dsm + 17408);          // 17408 B
    uint16_t* sBh = (uint16_t*)(dsm + 34816);          // 128*136*2 = 34816 B
    uint16_t* sBl = (uint16_t*)(dsm + 69632);          // 34816 B
    __shared__ float s_bias[128];

    const int tid = threadIdx.x;
    const int row0 = blockIdx.x * MT;

    if (tid < 128) s_bias[tid] = bc[tid];

    // ---- load + split-convert A tile (64 x 128 fp32) ----
    #pragma unroll 2
    for (int i = tid; i < MT * 32; i += 256) {         // 32 float4 per row
        int r = i >> 5, q = (i & 31) * 4;
        float4 x = make_float4(0.f, 0.f, 0.f, 0.f);
        if (row0 + r < VOCAB) x = *(const float4*)(emb + (size_t)(row0 + r) * 128 + q);
        split_store(sAh, sAl, r * SAS + q, x);
    }
    // ---- load + split-convert B = W_c (128 x 128 fp32) ----
    #pragma unroll 4
    for (int i = tid; i < 128 * 32; i += 256) {
        int r = i >> 5, q = (i & 31) * 4;
        float4 w = *(const float4*)(Wc + (size_t)r * 128 + q);
        split_store(sBh, sBl, r * SAS + q, w);
    }
    __syncthreads();

    const int warp = tid >> 5, lane = tid & 31;
    const int grp = lane >> 2, t4 = lane & 3;
    const int m0 = (warp & 1) * 32;
    const int n0 = (warp >> 1) * 32;

    float acc[2][4][4];
    #pragma unroll
    for (int mt = 0; mt < 2; mt++)
        #pragma unroll
        for (int nt = 0; nt < 4; nt++)
            #pragma unroll
            for (int j = 0; j < 4; j++) acc[mt][nt][j] = 0.f;

    #pragma unroll
    for (int ks = 0; ks < 8; ks++) {
        const int k0 = ks * 16;
        uint32_t ah[2][4], al[2][4];
        #pragma unroll
        for (int mt = 0; mt < 2; mt++) {
            int rb = (m0 + mt * 16 + grp) * SAS + k0 + t4 * 2;
            ah[mt][0] = *(const uint32_t*)(sAh + rb);
            ah[mt][1] = *(const uint32_t*)(sAh + rb + 8 * SAS);
            ah[mt][2] = *(const uint32_t*)(sAh + rb + 8);
            ah[mt][3] = *(const uint32_t*)(sAh + rb + 8 * SAS + 8);
            al[mt][0] = *(const uint32_t*)(sAl + rb);
            al[mt][1] = *(const uint32_t*)(sAl + rb + 8 * SAS);
            al[mt][2] = *(const uint32_t*)(sAl + rb + 8);
            al[mt][3] = *(const uint32_t*)(sAl + rb + 8 * SAS + 8);
        }
        uint32_t bh[4][2], bl[4][2];
        #pragma unroll
        for (int nt = 0; nt < 4; nt++) {
            int rb = (n0 + nt * 8 + grp) * SAS + k0 + t4 * 2;
            bh[nt][0] = *(const uint32_t*)(sBh + rb);
            bh[nt][1] = *(const uint32_t*)(sBh + rb + 8);
            bl[nt][0] = *(const uint32_t*)(sBl + rb);
            bl[nt][1] = *(const uint32_t*)(sBl + rb + 8);
        }
        #pragma unroll
        for (int mt = 0; mt < 2; mt++)
            #pragma unroll
            for (int nt = 0; nt < 4; nt++) {
                MMA16816(acc[mt][nt], ah[mt], bh[nt]);
                MMA16816(acc[mt][nt], ah[mt], bl[nt]);
                MMA16816(acc[mt][nt], al[mt], bh[nt]);
            }
    }

    // ---- epilogue: D + bias -> g_P ----
    #pragma unroll
    for (int mt = 0; mt < 2; mt++) {
        #pragma unroll
        for (int nt = 0; nt < 4; nt++) {
            int col = n0 + nt * 8 + t4 * 2;
            float b0 = s_bias[col], b1 = s_bias[col + 1];
            int r_lo = row0 + m0 + mt * 16 + grp;
            if (r_lo < VOCAB) {
                float2 v = make_float2(acc[mt][nt][0] + b0, acc[mt][nt][1] + b1);
                *(float2*)(g_P + (size_t)r_lo * 128 + col) = v;
            }
            int r_hi = r_lo + 8;
            if (r_hi < VOCAB) {
                float2 v = make_float2(acc[mt][nt][2] + b0, acc[mt][nt][3] + b1);
                *(float2*)(g_P + (size_t)r_hi * 128 + col) = v;
            }
        }
    }
}

// ---------------------------------------------------------------------------
// Kernel B: per (batch, channel-half) CTA: bottom-up subtree sums + max.
//   grid = BS*2, 512 threads. ch = tid&63, grp = tid>>6 (0..7).
//   Tokens staged in smem; 28 KB smem.
// ---------------------------------------------------------------------------
__global__ void __launch_bounds__(512) tree_kernel(const int* __restrict__ tokens,
                                                   float* __restrict__ out) {
    __shared__ int   stok[1024];        //  4 KB
    __shared__ float bufA[64 * 64];     // 16 KB
    __shared__ float bufB[32 * 64];     //  8 KB

    const int bh   = blockIdx.x;
    const int b    = bh >> 1;
    const int chb  = (bh & 1) << 6;
    const int tid  = threadIdx.x;
    const int ch   = tid & 63;
    const int grp  = tid >> 6;          // 0..7
    const int* tokrow = tokens + (size_t)b * NNODES;

    for (int i = tid; i < NNODES; i += 512) stok[i] = tokrow[i];
    __syncthreads();

    const float* Pc = g_P + chb + ch;
    float maxv = -3.4e38f;

    // fused levels 9..6: 64 subtrees rooted at level-6 nodes q = 63+m
    #pragma unroll
    for (int mi = 0; mi < 8; mi++) {
        int m = grp + mi * 8;
        int q = 63 + m;
        int b2 = 2 * q + 1, b4 = 4 * q + 3, b8 = 8 * q + 7;
        float v[15];
        v[0] = __ldg(Pc + (size_t)stok[q] * 128);
        #pragma unroll
        for (int j = 0; j < 2; j++) v[1 + j] = __ldg(Pc + (size_t)stok[b2 + j] * 128);
        #pragma unroll
        for (int j = 0; j < 4; j++) v[3 + j] = __ldg(Pc + (size_t)stok[b4 + j] * 128);
        #pragma unroll
        for (int j = 0; j < 8; j++) v[7 + j] = __ldg(Pc + (size_t)stok[b8 + j] * 128);

        float s8[4];
        #pragma unroll
        for (int j = 0; j < 4; j++) {
            float lft = v[7 + 2 * j], rgt = v[8 + 2 * j];
            maxv = fmaxf(maxv, fmaxf(lft, rgt));
            s8[j] = v[3 + j] + lft + rgt;
            maxv = fmaxf(maxv, s8[j]);
        }
        float s70 = v[1] + s8[0] + s8[1];
        float s71 = v[2] + s8[2] + s8[3];
        maxv = fmaxf(maxv, fmaxf(s70, s71));
        float s6 = v[0] + s70 + s71;
        maxv = fmaxf(maxv, s6);
        bufA[m * 64 + ch] = s6;
    }
    __syncthreads();

    for (int i = grp; i < 32; i += 8) {          // l5: A(64)->B(32)
        float v = bufA[(2 * i) * 64 + ch] + bufA[(2 * i + 1) * 64 + ch]
                + __ldg(Pc + (size_t)stok[31 + i] * 128);
        maxv = fmaxf(maxv, v);
        bufB[i * 64 + ch] = v;
    }
    __syncthreads();
    for (int i = grp; i < 16; i += 8) {          // l4: B(32)->A(16)
        float v = bufB[(2 * i) * 64 + ch] + bufB[(2 * i + 1) * 64 + ch]
                + __ldg(Pc + (size_t)stok[15 + i] * 128);
        maxv = fmaxf(maxv, v);
        bufA[i * 64 + ch] = v;
    }
    __syncthreads();
    {                                            // l3: A(16)->B(8)
        int i = grp;
        float v = bufA[(2 * i) * 64 + ch] + bufA[(2 * i + 1) * 64 + ch]
                + __ldg(Pc + (size_t)stok[7 + i] * 128);
        maxv = fmaxf(maxv, v);
        bufB[i * 64 + ch] = v;
    }
    __syncthreads();
    if (grp < 4) {                               // l2: B(8)->A(4)
        int i = grp;
        float v = bufB[(2 * i) * 64 + ch] + bufB[(2 * i + 1) * 64 + ch]
                + __ldg(Pc + (size_t)stok[3 + i] * 128);
        maxv = fmaxf(maxv, v);
        bufA[i * 64 + ch] = v;
    }
    __syncthreads();
    if (grp < 2) {                               // l1: A(4)->B(2)
        int i = grp;
        float v = bufA[(2 * i) * 64 + ch] + bufA[(2 * i + 1) * 64 + ch]
                + __ldg(Pc + (size_t)stok[1 + i] * 128);
        maxv = fmaxf(maxv, v);
        bufB[i * 64 + ch] = v;
    }
    __syncthreads();
    if (grp == 0) {                              // l0: root
        float v = bufB[ch] + bufB[64 + ch] + __ldg(Pc + (size_t)stok[0] * 128);
        maxv = fmaxf(maxv, v);
    }

    // cross-group max (reuse bufA; 512 floats)
    bufA[tid] = maxv;
    __syncthreads();
    if (grp == 0) {
        float m0 = fmaxf(bufA[ch],        bufA[64 + ch]);
        float m1 = fmaxf(bufA[128 + ch],  bufA[192 + ch]);
        float m2 = fmaxf(bufA[256 + ch],  bufA[320 + ch]);
        float m3 = fmaxf(bufA[384 + ch],  bufA[448 + ch]);
        out[(size_t)b * 128 + chb + ch] = fmaxf(fmaxf(m0, m1), fmaxf(m2, m3));
    }
}

// ---------------------------------------------------------------------------
// kernel_launch
// ---------------------------------------------------------------------------
extern "C" void kernel_launch(void* const* d_in, const int* in_sizes, int n_in,
                              void* d_out, int out_size) {
    const int*   tokens = (const int*)d_in[0];
    const float* emb    = (const float*)d_in[1];
    const float* Wc     = (const float*)d_in[2];
    const float* bc     = (const float*)d_in[3];
    float*       out    = (float*)d_out;

    const int smemA = 2 * 17408 + 2 * 34816;   // 104448 B
    cudaFuncSetAttribute(pmat_kernel, cudaFuncAttributeMaxDynamicSharedMemorySize, smemA);

    const int gridA = (VOCAB + MT - 1) / MT;   // 469
    pmat_kernel<<<gridA, 256, smemA>>>(emb, Wc, bc);
    tree_kernel<<<BS * 2, 512>>>(tokens, out);
}

// round 5
// speedup vs baseline: 3.6233x; 1.0727x over previous
#include <cuda_runtime.h>
#include <cuda_bf16.h>
#include <cstdint>

#define VOCAB 30000
#define EMB 128
#define ENC 128
#define BS 256
#define NNODES 1023

// Precomputed P[t][o] = dot(emb[t,:], W_c[o,:]) + b_c[o]   (15.36 MB scratch)
__device__ float g_P[VOCAB * ENC];
// Pre-split W (bf16 hi/lo), row-major [o][k]
__device__ __nv_bfloat16 g_Wh[ENC * EMB];
__device__ __nv_bfloat16 g_Wl[ENC * EMB];

// ---------------------------------------------------------------------------
// Kernel 0: one-shot W split (fp32 -> bf16 hi + bf16 residual lo)
// ---------------------------------------------------------------------------
__global__ void wsplit_kernel(const float* __restrict__ Wc) {
    int i = (blockIdx.x * 256 + threadIdx.x) * 4;   // 16 blocks x 256 thr x 4
    float4 w = *(const float4*)(Wc + i);
    __nv_bfloat162 h01 = __floats2bfloat162_rn(w.x, w.y);
    __nv_bfloat162 h23 = __floats2bfloat162_rn(w.z, w.w);
    __nv_bfloat162 l01 = __floats2bfloat162_rn(w.x - __bfloat162float(h01.x),
                                               w.y - __bfloat162float(h01.y));
    __nv_bfloat162 l23 = __floats2bfloat162_rn(w.z - __bfloat162float(h23.x),
                                               w.w - __bfloat162float(h23.y));
    *(uint2*)(g_Wh + i) = make_uint2(*(uint32_t*)&h01, *(uint32_t*)&h23);
    *(uint2*)(g_Wl + i) = make_uint2(*(uint32_t*)&l01, *(uint32_t*)&l23);
}

// ---------------------------------------------------------------------------
// Kernel A: P = emb @ W_c^T + b_c via mma.sync m16n8k16 bf16 (HMMA),
// split-precision: emb=eh+el, W=wh+wl, D = eh*wh + eh*wl + el*wh (fp32 acc).
//   CTA: 256 thr (8 warps), tile M=64 x N=128 x K=128.
// ---------------------------------------------------------------------------
#define MT 64
#define SAS 136   // smem row stride in bf16 elements

#define MMA16816(c, a, b)                                                   \
    asm("mma.sync.aligned.m16n8k16.row.col.f32.bf16.bf16.f32 "              \
        "{%0,%1,%2,%3}, {%4,%5,%6,%7}, {%8,%9}, {%0,%1,%2,%3};"             \
        : "+f"((c)[0]), "+f"((c)[1]), "+f"((c)[2]), "+f"((c)[3])            \
        : "r"((a)[0]), "r"((a)[1]), "r"((a)[2]), "r"((a)[3]),               \
          "r"((b)[0]), "r"((b)[1]))

__device__ __forceinline__ void split_store(uint16_t* __restrict__ h,
                                            uint16_t* __restrict__ l,
                                            int off, float4 x) {
    __nv_bfloat162 h01 = __floats2bfloat162_rn(x.x, x.y);
    __nv_bfloat162 h23 = __floats2bfloat162_rn(x.z, x.w);
    __nv_bfloat162 l01 = __floats2bfloat162_rn(x.x - __bfloat162float(h01.x),
                                               x.y - __bfloat162float(h01.y));
    __nv_bfloat162 l23 = __floats2bfloat162_rn(x.z - __bfloat162float(h23.x),
                                               x.w - __bfloat162float(h23.y));
    *(uint2*)(h + off) = make_uint2(*(uint32_t*)&h01, *(uint32_t*)&h23);
    *(uint2*)(l + off) = make_uint2(*(uint32_t*)&l01, *(uint32_t*)&l23);
}

__global__ void __launch_bounds__(256) pmat_kernel(const float* __restrict__ emb,
                                                   const float* __restrict__ bc) {
    extern __shared__ __align__(16) char dsm[];
    uint16_t* sAh = (uint16_t*)dsm;                    // 64*136*2  = 17408 B
    uint16_t* sAl = (uint16_t*)(dsm + 17408);          // 17408 B
    uint16_t* sBh = (uint16_t*)(dsm + 34816);          // 128*136*2 = 34816 B
    uint16_t* sBl = (uint16_t*)(dsm + 69632);          // 34816 B
    __shared__ float s_bias[128];

    const int tid = threadIdx.x;
    const int row0 = blockIdx.x * MT;

    if (tid < 128) s_bias[tid] = bc[tid];

    // ---- A tile: load fp32, split to bf16 hi/lo ----
    #pragma unroll 2
    for (int i = tid; i < MT * 32; i += 256) {         // 32 float4 per row
        int r = i >> 5, q = (i & 31) * 4;
        float4 x = make_float4(0.f, 0.f, 0.f, 0.f);
        if (row0 + r < VOCAB) x = *(const float4*)(emb + (size_t)(row0 + r) * 128 + q);
        split_store(sAh, sAl, r * SAS + q, x);
    }
    // ---- B tiles: pure bf16 copy from pre-split g_Wh/g_Wl ----
    const uint4* Wh4 = (const uint4*)g_Wh;   // 8 bf16 per uint4, 2048 total
    const uint4* Wl4 = (const uint4*)g_Wl;
    #pragma unroll 4
    for (int i = tid; i < 2048; i += 256) {
        int r = i >> 4, q = (i & 15) * 8;
        *(uint4*)(sBh + r * SAS + q) = Wh4[i];
        *(uint4*)(sBl + r * SAS + q) = Wl4[i];
    }
    __syncthreads();

    const int warp = tid >> 5, lane = tid & 31;
    const int grp = lane >> 2, t4 = lane & 3;
    const int m0 = (warp & 1) * 32;
    const int n0 = (warp >> 1) * 32;

    float acc[2][4][4];
    #pragma unroll
    for (int mt = 0; mt < 2; mt++)
        #pragma unroll
        for (int nt = 0; nt < 4; nt++)
            #pragma unroll
            for (int j = 0; j < 4; j++) acc[mt][nt][j] = 0.f;

    #pragma unroll
    for (int ks = 0; ks < 8; ks++) {
        const int k0 = ks * 16;
        uint32_t ah[2][4], al[2][4];
        #pragma unroll
        for (int mt = 0; mt < 2; mt++) {
            int rb = (m0 + mt * 16 + grp) * SAS + k0 + t4 * 2;
            ah[mt][0] = *(const uint32_t*)(sAh + rb);
            ah[mt][1] = *(const uint32_t*)(sAh + rb + 8 * SAS);
            ah[mt][2] = *(const uint32_t*)(sAh + rb + 8);
            ah[mt][3] = *(const uint32_t*)(sAh + rb + 8 * SAS + 8);
            al[mt][0] = *(const uint32_t*)(sAl + rb);
            al[mt][1] = *(const uint32_t*)(sAl + rb + 8 * SAS);
            al[mt][2] = *(const uint32_t*)(sAl + rb + 8);
            al[mt][3] = *(const uint32_t*)(sAl + rb + 8 * SAS + 8);
        }
        uint32_t bh[4][2], bl[4][2];
        #pragma unroll
        for (int nt = 0; nt < 4; nt++) {
            int rb = (n0 + nt * 8 + grp) * SAS + k0 + t4 * 2;
            bh[nt][0] = *(const uint32_t*)(sBh + rb);
            bh[nt][1] = *(const uint32_t*)(sBh + rb + 8);
            bl[nt][0] = *(const uint32_t*)(sBl + rb);
            bl[nt][1] = *(const uint32_t*)(sBl + rb + 8);
        }
        #pragma unroll
        for (int mt = 0; mt < 2; mt++)
            #pragma unroll
            for (int nt = 0; nt < 4; nt++) {
                MMA16816(acc[mt][nt], ah[mt], bh[nt]);
                MMA16816(acc[mt][nt], ah[mt], bl[nt]);
                MMA16816(acc[mt][nt], al[mt], bh[nt]);
            }
    }

    // ---- epilogue: D + bias -> g_P ----
    #pragma unroll
    for (int mt = 0; mt < 2; mt++) {
        #pragma unroll
        for (int nt = 0; nt < 4; nt++) {
            int col = n0 + nt * 8 + t4 * 2;
            float b0 = s_bias[col], b1 = s_bias[col + 1];
            int r_lo = row0 + m0 + mt * 16 + grp;
            if (r_lo < VOCAB) {
                float2 v = make_float2(acc[mt][nt][0] + b0, acc[mt][nt][1] + b1);
                *(float2*)(g_P + (size_t)r_lo * 128 + col) = v;
            }
            int r_hi = r_lo + 8;
            if (r_hi < VOCAB) {
                float2 v = make_float2(acc[mt][nt][2] + b0, acc[mt][nt][3] + b1);
                *(float2*)(g_P + (size_t)r_hi * 128 + col) = v;
            }
        }
    }
}

// ---------------------------------------------------------------------------
// Kernel B: per (batch, channel-half) CTA: bottom-up subtree sums + max.
//   grid = BS*2, 512 threads. float2 per thread: lane covers ch-pair 2*lane,
//   grp = tid>>5 (0..15) picks nodes. One LDG.64 = full 256 B node row/warp.
// ---------------------------------------------------------------------------
__device__ __forceinline__ float2 f2add(float2 a, float2 b) {
    return make_float2(a.x + b.x, a.y + b.y);
}
__device__ __forceinline__ float2 f2max(float2 a, float2 b) {
    return make_float2(fmaxf(a.x, b.x), fmaxf(a.y, b.y));
}

__global__ void __launch_bounds__(512) tree_kernel(const int* __restrict__ tokens,
                                                   float* __restrict__ out) {
    __shared__ int    stok[1024];        //  4 KB
    __shared__ float2 bufA[64 * 32];     // 16 KB
    __shared__ float2 bufB[32 * 32];     //  8 KB

    const int bh   = blockIdx.x;
    const int b    = bh >> 1;
    const int chb  = (bh & 1) << 6;
    const int tid  = threadIdx.x;
    const int lane = tid & 31;
    const int grp  = tid >> 5;           // 0..15
    const int* tokrow = tokens + (size_t)b * NNODES;

    for (int i = tid; i < NNODES; i += 512) stok[i] = tokrow[i];
    __syncthreads();

    const float2* Pc = (const float2*)(g_P + chb) + lane;  // node t -> Pc[t*64]
    float2 maxv = make_float2(-3.4e38f, -3.4e38f);

    // fused levels 9..6: 64 subtrees rooted at level-6 nodes q = 63+m
    #pragma unroll
    for (int mi = 0; mi < 4; mi++) {
        int m = grp + mi * 16;
        int q = 63 + m;
        int b2 = 2 * q + 1, b4 = 4 * q + 3, b8 = 8 * q + 7;
        float2 v[15];
        v[0] = __ldg(Pc + (size_t)stok[q] * 64);
        #pragma unroll
        for (int j = 0; j < 2; j++) v[1 + j] = __ldg(Pc + (size_t)stok[b2 + j] * 64);
        #pragma unroll
        for (int j = 0; j < 4; j++) v[3 + j] = __ldg(Pc + (size_t)stok[b4 + j] * 64);
        #pragma unroll
        for (int j = 0; j < 8; j++) v[7 + j] = __ldg(Pc + (size_t)stok[b8 + j] * 64);

        float2 s8[4];
        #pragma unroll
        for (int j = 0; j < 4; j++) {
            float2 lft = v[7 + 2 * j], rgt = v[8 + 2 * j];
            maxv = f2max(maxv, f2max(lft, rgt));
            s8[j] = f2add(v[3 + j], f2add(lft, rgt));
            maxv = f2max(maxv, s8[j]);
        }
        float2 s70 = f2add(v[1], f2add(s8[0], s8[1]));
        float2 s71 = f2add(v[2], f2add(s8[2], s8[3]));
        maxv = f2max(maxv, f2max(s70, s71));
        float2 s6 = f2add(v[0], f2add(s70, s71));
        maxv = f2max(maxv, s6);
        bufA[m * 32 + lane] = s6;
    }
    __syncthreads();

    #pragma unroll
    for (int ii = 0; ii < 2; ii++) {             // l5: A(64)->B(32)
        int i = grp + ii * 16;
        float2 v = f2add(f2add(bufA[(2 * i) * 32 + lane], bufA[(2 * i + 1) * 32 + lane]),
                         __ldg(Pc + (size_t)stok[31 + i] * 64));
        maxv = f2max(maxv, v);
        bufB[i * 32 + lane] = v;
    }
    __syncthreads();
    {                                            // l4: B(32)->A(16)
        int i = grp;
        float2 v = f2add(f2add(bufB[(2 * i) * 32 + lane], bufB[(2 * i + 1) * 32 + lane]),
                         __ldg(Pc + (size_t)stok[15 + i] * 64));
        maxv = f2max(maxv, v);
        bufA[i * 32 + lane] = v;
    }
    __syncthreads();
    if (grp < 8) {                               // l3: A(16)->B(8)
        int i = grp;
        float2 v = f2add(f2add(bufA[(2 * i) * 32 + lane], bufA[(2 * i + 1) * 32 + lane]),
                         __ldg(Pc + (size_t)stok[7 + i] * 64));
        maxv = f2max(maxv, v);
        bufB[i * 32 + lane] = v;
    }
    __syncthreads();
    if (grp < 4) {                               // l2: B(8)->A(4)
        int i = grp;
        float2 v = f2add(f2add(bufB[(2 * i) * 32 + lane], bufB[(2 * i + 1) * 32 + lane]),
                         __ldg(Pc + (size_t)stok[3 + i] * 64));
        maxv = f2max(maxv, v);
        bufA[i * 32 + lane] = v;
    }
    __syncthreads();
    if (grp < 2) {                               // l1: A(4)->B(2)
        int i = grp;
        float2 v = f2add(f2add(bufA[(2 * i) * 32 + lane], bufA[(2 * i + 1) * 32 + lane]),
                         __ldg(Pc + (size_t)stok[1 + i] * 64));
        maxv = f2max(maxv, v);
        bufB[i * 32 + lane] = v;
    }
    __syncthreads();
    if (grp == 0) {                              // l0: root
        float2 v = f2add(f2add(bufB[lane], bufB[32 + lane]),
                         __ldg(Pc + (size_t)stok[0] * 64));
        maxv = f2max(maxv, v);
    }

    // cross-group max (reuse bufA: [grp][lane])
    bufA[grp * 32 + lane] = maxv;
    __syncthreads();
    if (grp == 0) {
        float2 m = bufA[lane];
        #pragma unroll
        for (int g = 1; g < 16; g++) m = f2max(m, bufA[g * 32 + lane]);
        *(float2*)(out + (size_t)b * 128 + chb + 2 * lane) = m;
    }
}

// ---------------------------------------------------------------------------
// kernel_launch
// ---------------------------------------------------------------------------
extern "C" void kernel_launch(void* const* d_in, const int* in_sizes, int n_in,
                              void* d_out, int out_size) {
    const int*   tokens = (const int*)d_in[0];
    const float* emb    = (const float*)d_in[1];
    const float* Wc     = (const float*)d_in[2];
    const float* bc     = (const float*)d_in[3];
    float*       out    = (float*)d_out;

    const int smemA = 2 * 17408 + 2 * 34816;   // 104448 B
    cudaFuncSetAttribute(pmat_kernel, cudaFuncAttributeMaxDynamicSharedMemorySize, smemA);

    wsplit_kernel<<<16, 256>>>(Wc);
    const int gridA = (VOCAB + MT - 1) / MT;   // 469
    pmat_kernel<<<gridA, 256, smemA>>>(emb, bc);
    tree_kernel<<<BS * 2, 512>>>(tokens, out);
}

// round 6
// speedup vs baseline: 3.6270x; 1.0010x over previous
#include <cuda_runtime.h>
#include <cuda_bf16.h>
#include <cstdint>

#define VOCAB 30000
#define EMB 128
#define ENC 128
#define BS 256
#define NNODES 1023

// Precomputed P[t][o] = dot(emb[t,:], W_c[o,:]) + b_c[o]   (15.36 MB scratch)
__device__ float g_P[VOCAB * ENC];
// Pre-split W (bf16 hi/lo), row-major [o][k]
__device__ __nv_bfloat16 g_Wh[ENC * EMB];
__device__ __nv_bfloat16 g_Wl[ENC * EMB];
// W-ready flag (set once by pmat CTA 0; stays set across graph replays —
// CTA 0 rewrites byte-identical data each replay, so the race is benign).
__device__ int g_wflag;

// ---------------------------------------------------------------------------
// Kernel A: P = emb @ W_c^T + b_c via mma.sync m16n8k16 bf16 (HMMA),
// split-precision: emb=eh+el, W=wh+wl, D = eh*wh + eh*wl + el*wh (fp32 acc).
//   CTA: 256 thr (8 warps), tile M=64 x N=128 x K=128.
//   CTA 0 additionally produces the global W bf16 hi/lo split (flag-published).
// ---------------------------------------------------------------------------
#define MT 64
#define SAS 136   // smem row stride in bf16 elements

#define MMA16816(c, a, b)                                                   \
    asm("mma.sync.aligned.m16n8k16.row.col.f32.bf16.bf16.f32 "              \
        "{%0,%1,%2,%3}, {%4,%5,%6,%7}, {%8,%9}, {%0,%1,%2,%3};"             \
        : "+f"((c)[0]), "+f"((c)[1]), "+f"((c)[2]), "+f"((c)[3])            \
        : "r"((a)[0]), "r"((a)[1]), "r"((a)[2]), "r"((a)[3]),               \
          "r"((b)[0]), "r"((b)[1]))

__device__ __forceinline__ void split4(float4 x, uint2& h, uint2& l) {
    __nv_bfloat162 h01 = __floats2bfloat162_rn(x.x, x.y);
    __nv_bfloat162 h23 = __floats2bfloat162_rn(x.z, x.w);
    __nv_bfloat162 l01 = __floats2bfloat162_rn(x.x - __bfloat162float(h01.x),
                                               x.y - __bfloat162float(h01.y));
    __nv_bfloat162 l23 = __floats2bfloat162_rn(x.z - __bfloat162float(h23.x),
                                               x.w - __bfloat162float(h23.y));
    h = make_uint2(*(uint32_t*)&h01, *(uint32_t*)&h23);
    l = make_uint2(*(uint32_t*)&l01, *(uint32_t*)&l23);
}

__global__ void __launch_bounds__(256) pmat_kernel(const float* __restrict__ emb,
                                                   const float* __restrict__ Wc,
                                                   const float* __restrict__ bc) {
    extern __shared__ __align__(16) char dsm[];
    uint16_t* sAh = (uint16_t*)dsm;                    // 64*136*2  = 17408 B
    uint16_t* sAl = (uint16_t*)(dsm + 17408);          // 17408 B
    uint16_t* sBh = (uint16_t*)(dsm + 34816);          // 128*136*2 = 34816 B
    uint16_t* sBl = (uint16_t*)(dsm + 69632);          // 34816 B
    __shared__ float s_bias[128];

    const int tid = threadIdx.x;
    const int row0 = blockIdx.x * MT;

    // ---- CTA 0: produce global W split FIRST (unblocks everyone else) ----
    if (blockIdx.x == 0) {
        #pragma unroll 4
        for (int i4 = tid; i4 < 4096; i4 += 256) {     // 16384 elems / 4
            float4 w = *(const float4*)(Wc + i4 * 4);
            uint2 h, l;
            split4(w, h, l);
            *(uint2*)(g_Wh + i4 * 4) = h;
            *(uint2*)(g_Wl + i4 * 4) = l;
        }
        __syncthreads();
        __threadfence();
        if (tid == 0) atomicExch(&g_wflag, 1);
    }

    if (tid < 128) s_bias[tid] = bc[tid];

    // ---- A tile: load fp32, split to bf16 hi/lo (no W dependency) ----
    #pragma unroll 2
    for (int i = tid; i < MT * 32; i += 256) {         // 32 float4 per row
        int r = i >> 5, q = (i & 31) * 4;
        float4 x = make_float4(0.f, 0.f, 0.f, 0.f);
        if (row0 + r < VOCAB) x = *(const float4*)(emb + (size_t)(row0 + r) * 128 + q);
        uint2 h, l;
        split4(x, h, l);
        *(uint2*)(sAh + r * SAS + q) = h;
        *(uint2*)(sAl + r * SAS + q) = l;
    }

    // ---- wait for W split (already done for CTA 0 / later waves) ----
    if (blockIdx.x != 0) {
        if (tid == 0) {
            while (atomicAdd(&g_wflag, 0) == 0) __nanosleep(64);
        }
        __syncthreads();   // all threads gated on thread 0's acquire
    }

    // ---- B tiles: pure bf16 copy from pre-split g_Wh/g_Wl ----
    const uint4* Wh4 = (const uint4*)g_Wh;   // 8 bf16 per uint4, 2048 total
    const uint4* Wl4 = (const uint4*)g_Wl;
    #pragma unroll 4
    for (int i = tid; i < 2048; i += 256) {
        int r = i >> 4, q = (i & 15) * 8;
        *(uint4*)(sBh + r * SAS + q) = Wh4[i];
        *(uint4*)(sBl + r * SAS + q) = Wl4[i];
    }
    __syncthreads();

    const int warp = tid >> 5, lane = tid & 31;
    const int grp = lane >> 2, t4 = lane & 3;
    const int m0 = (warp & 1) * 32;
    const int n0 = (warp >> 1) * 32;

    float acc[2][4][4];
    #pragma unroll
    for (int mt = 0; mt < 2; mt++)
        #pragma unroll
        for (int nt = 0; nt < 4; nt++)
            #pragma unroll
            for (int j = 0; j < 4; j++) acc[mt][nt][j] = 0.f;

    #pragma unroll
    for (int ks = 0; ks < 8; ks++) {
        const int k0 = ks * 16;
        uint32_t ah[2][4], al[2][4];
        #pragma unroll
        for (int mt = 0; mt < 2; mt++) {
            int rb = (m0 + mt * 16 + grp) * SAS + k0 + t4 * 2;
            ah[mt][0] = *(const uint32_t*)(sAh + rb);
            ah[mt][1] = *(const uint32_t*)(sAh + rb + 8 * SAS);
            ah[mt][2] = *(const uint32_t*)(sAh + rb + 8);
            ah[mt][3] = *(const uint32_t*)(sAh + rb + 8 * SAS + 8);
            al[mt][0] = *(const uint32_t*)(sAl + rb);
            al[mt][1] = *(const uint32_t*)(sAl + rb + 8 * SAS);
            al[mt][2] = *(const uint32_t*)(sAl + rb + 8);
            al[mt][3] = *(const uint32_t*)(sAl + rb + 8 * SAS + 8);
        }
        uint32_t bh[4][2], bl[4][2];
        #pragma unroll
        for (int nt = 0; nt < 4; nt++) {
            int rb = (n0 + nt * 8 + grp) * SAS + k0 + t4 * 2;
            bh[nt][0] = *(const uint32_t*)(sBh + rb);
            bh[nt][1] = *(const uint32_t*)(sBh + rb + 8);
            bl[nt][0] = *(const uint32_t*)(sBl + rb);
            bl[nt][1] = *(const uint32_t*)(sBl + rb + 8);
        }
        #pragma unroll
        for (int mt = 0; mt < 2; mt++)
            #pragma unroll
            for (int nt = 0; nt < 4; nt++) {
                MMA16816(acc[mt][nt], ah[mt], bh[nt]);
                MMA16816(acc[mt][nt], ah[mt], bl[nt]);
                MMA16816(acc[mt][nt], al[mt], bh[nt]);
            }
    }

    // ---- epilogue: D + bias -> g_P ----
    #pragma unroll
    for (int mt = 0; mt < 2; mt++) {
        #pragma unroll
        for (int nt = 0; nt < 4; nt++) {
            int col = n0 + nt * 8 + t4 * 2;
            float b0 = s_bias[col], b1 = s_bias[col + 1];
            int r_lo = row0 + m0 + mt * 16 + grp;
            if (r_lo < VOCAB) {
                float2 v = make_float2(acc[mt][nt][0] + b0, acc[mt][nt][1] + b1);
                *(float2*)(g_P + (size_t)r_lo * 128 + col) = v;
            }
            int r_hi = r_lo + 8;
            if (r_hi < VOCAB) {
                float2 v = make_float2(acc[mt][nt][2] + b0, acc[mt][nt][3] + b1);
                *(float2*)(g_P + (size_t)r_hi * 128 + col) = v;
            }
        }
    }
}

// ---------------------------------------------------------------------------
// Kernel B: per (batch, channel-half) CTA: bottom-up subtree sums + max.
//   grid = BS*2, 512 threads. float2 per thread: lane covers ch-pair 2*lane,
//   grp = tid>>5 (0..15) picks nodes. One LDG.64 = full 256 B node row/warp.
// ---------------------------------------------------------------------------
__device__ __forceinline__ float2 f2add(float2 a, float2 b) {
    return make_float2(a.x + b.x, a.y + b.y);
}
__device__ __forceinline__ float2 f2max(float2 a, float2 b) {
    return make_float2(fmaxf(a.x, b.x), fmaxf(a.y, b.y));
}

__global__ void __launch_bounds__(512) tree_kernel(const int* __restrict__ tokens,
                                                   float* __restrict__ out) {
    __shared__ int    stok[1024];        //  4 KB
    __shared__ float2 bufA[64 * 32];     // 16 KB
    __shared__ float2 bufB[32 * 32];     //  8 KB

    const int bh   = blockIdx.x;
    const int b    = bh >> 1;
    const int chb  = (bh & 1) << 6;
    const int tid  = threadIdx.x;
    const int lane = tid & 31;
    const int grp  = tid >> 5;           // 0..15
    const int* tokrow = tokens + (size_t)b * NNODES;

    for (int i = tid; i < NNODES; i += 512) stok[i] = tokrow[i];
    __syncthreads();

    const float2* Pc = (const float2*)(g_P + chb) + lane;  // node t -> Pc[t*64]
    float2 maxv = make_float2(-3.4e38f, -3.4e38f);

    // fused levels 9..6: 64 subtrees rooted at level-6 nodes q = 63+m
    #pragma unroll
    for (int mi = 0; mi < 4; mi++) {
        int m = grp + mi * 16;
        int q = 63 + m;
        int b2 = 2 * q + 1, b4 = 4 * q + 3, b8 = 8 * q + 7;
        float2 v[15];
        v[0] = __ldg(Pc + (size_t)stok[q] * 64);
        #pragma unroll
        for (int j = 0; j < 2; j++) v[1 + j] = __ldg(Pc + (size_t)stok[b2 + j] * 64);
        #pragma unroll
        for (int j = 0; j < 4; j++) v[3 + j] = __ldg(Pc + (size_t)stok[b4 + j] * 64);
        #pragma unroll
        for (int j = 0; j < 8; j++) v[7 + j] = __ldg(Pc + (size_t)stok[b8 + j] * 64);

        float2 s8[4];
        #pragma unroll
        for (int j = 0; j < 4; j++) {
            float2 lft = v[7 + 2 * j], rgt = v[8 + 2 * j];
            maxv = f2max(maxv, f2max(lft, rgt));
            s8[j] = f2add(v[3 + j], f2add(lft, rgt));
            maxv = f2max(maxv, s8[j]);
        }
        float2 s70 = f2add(v[1], f2add(s8[0], s8[1]));
        float2 s71 = f2add(v[2], f2add(s8[2], s8[3]));
        maxv = f2max(maxv, f2max(s70, s71));
        float2 s6 = f2add(v[0], f2add(s70, s71));
        maxv = f2max(maxv, s6);
        bufA[m * 32 + lane] = s6;
    }
    __syncthreads();

    #pragma unroll
    for (int ii = 0; ii < 2; ii++) {             // l5: A(64)->B(32)
        int i = grp + ii * 16;
        float2 v = f2add(f2add(bufA[(2 * i) * 32 + lane], bufA[(2 * i + 1) * 32 + lane]),
                         __ldg(Pc + (size_t)stok[31 + i] * 64));
        maxv = f2max(maxv, v);
        bufB[i * 32 + lane] = v;
    }
    __syncthreads();
    {                                            // l4: B(32)->A(16)
        int i = grp;
        float2 v = f2add(f2add(bufB[(2 * i) * 32 + lane], bufB[(2 * i + 1) * 32 + lane]),
                         __ldg(Pc + (size_t)stok[15 + i] * 64));
        maxv = f2max(maxv, v);
        bufA[i * 32 + lane] = v;
    }
    __syncthreads();
    if (grp < 8) {                               // l3: A(16)->B(8)
        int i = grp;
        float2 v = f2add(f2add(bufA[(2 * i) * 32 + lane], bufA[(2 * i + 1) * 32 + lane]),
                         __ldg(Pc + (size_t)stok[7 + i] * 64));
        maxv = f2max(maxv, v);
        bufB[i * 32 + lane] = v;
    }
    __syncthreads();
    if (grp < 4) {                               // l2: B(8)->A(4)
        int i = grp;
        float2 v = f2add(f2add(bufB[(2 * i) * 32 + lane], bufB[(2 * i + 1) * 32 + lane]),
                         __ldg(Pc + (size_t)stok[3 + i] * 64));
        maxv = f2max(maxv, v);
        bufA[i * 32 + lane] = v;
    }
    __syncthreads();
    if (grp < 2) {                               // l1: A(4)->B(2)
        int i = grp;
        float2 v = f2add(f2add(bufA[(2 * i) * 32 + lane], bufA[(2 * i + 1) * 32 + lane]),
                         __ldg(Pc + (size_t)stok[1 + i] * 64));
        maxv = f2max(maxv, v);
        bufB[i * 32 + lane] = v;
    }
    __syncthreads();
    if (grp == 0) {                              // l0: root
        float2 v = f2add(f2add(bufB[lane], bufB[32 + lane]),
                         __ldg(Pc + (size_t)stok[0] * 64));
        maxv = f2max(maxv, v);
    }

    // cross-group max (reuse bufA: [grp][lane])
    bufA[grp * 32 + lane] = maxv;
    __syncthreads();
    if (grp == 0) {
        float2 m = bufA[lane];
        #pragma unroll
        for (int g = 1; g < 16; g++) m = f2max(m, bufA[g * 32 + lane]);
        *(float2*)(out + (size_t)b * 128 + chb + 2 * lane) = m;
    }
}

// ---------------------------------------------------------------------------
// kernel_launch
// ---------------------------------------------------------------------------
extern "C" void kernel_launch(void* const* d_in, const int* in_sizes, int n_in,
                              void* d_out, int out_size) {
    const int*   tokens = (const int*)d_in[0];
    const float* emb    = (const float*)d_in[1];
    const float* Wc     = (const float*)d_in[2];
    const float* bc     = (const float*)d_in[3];
    float*       out    = (float*)d_out;

    const int smemA = 2 * 17408 + 2 * 34816;   // 104448 B
    cudaFuncSetAttribute(pmat_kernel, cudaFuncAttributeMaxDynamicSharedMemorySize, smemA);

    const int gridA = (VOCAB + MT - 1) / MT;   // 469
    pmat_kernel<<<gridA, 256, smemA>>>(emb, Wc, bc);
    tree_kernel<<<BS * 2, 512>>>(tokens, out);
}

// round 7
// speedup vs baseline: 3.8478x; 1.0609x over previous
#include <cuda_runtime.h>
#include <cuda_bf16.h>
#include <cstdint>

#define VOCAB 30000
#define EMB 128
#define ENC 128
#define BS 256
#define NNODES 1023

// Precomputed P[t][o] = dot(emb[t,:], W_c[o,:]) + b_c[o]   (15.36 MB scratch)
__device__ float g_P[VOCAB * ENC];

// ---------------------------------------------------------------------------
// Kernel A: P = emb @ W_c^T + b_c via mma.sync m16n8k16 bf16 (HMMA),
// split-precision: emb=eh+el, W=wh+wl, D = eh*wh + eh*wl + el*wh (fp32 acc).
//   CTA: 256 thr (8 warps), tile M=64 x N=128 x K=128.
//   Fragments via ldmatrix.x4 (4x fewer smem instructions than LDS.32 path).
// ---------------------------------------------------------------------------
#define MT 64
#define SAS 136   // smem row stride in bf16 elements (272 B: ldmatrix conflict-free)

#define MMA16816(c, a, b)                                                   \
    asm("mma.sync.aligned.m16n8k16.row.col.f32.bf16.bf16.f32 "              \
        "{%0,%1,%2,%3}, {%4,%5,%6,%7}, {%8,%9}, {%0,%1,%2,%3};"             \
        : "+f"((c)[0]), "+f"((c)[1]), "+f"((c)[2]), "+f"((c)[3])            \
        : "r"((a)[0]), "r"((a)[1]), "r"((a)[2]), "r"((a)[3]),               \
          "r"((b)[0]), "r"((b)[1]))

#define LDMX4(r, addr)                                                      \
    asm volatile("ldmatrix.sync.aligned.m8n8.x4.shared.b16 "                \
                 "{%0,%1,%2,%3}, [%4];"                                     \
                 : "=r"((r)[0]), "=r"((r)[1]), "=r"((r)[2]), "=r"((r)[3])   \
                 : "r"(addr))

__device__ __forceinline__ uint32_t su32(const void* p) {
    return (uint32_t)__cvta_generic_to_shared(p);
}

__device__ __forceinline__ void split_store(uint16_t* __restrict__ h,
                                            uint16_t* __restrict__ l,
                                            int off, float4 x) {
    __nv_bfloat162 h01 = __floats2bfloat162_rn(x.x, x.y);
    __nv_bfloat162 h23 = __floats2bfloat162_rn(x.z, x.w);
    __nv_bfloat162 l01 = __floats2bfloat162_rn(x.x - __bfloat162float(h01.x),
                                               x.y - __bfloat162float(h01.y));
    __nv_bfloat162 l23 = __floats2bfloat162_rn(x.z - __bfloat162float(h23.x),
                                               x.w - __bfloat162float(h23.y));
    *(uint2*)(h + off) = make_uint2(*(uint32_t*)&h01, *(uint32_t*)&h23);
    *(uint2*)(l + off) = make_uint2(*(uint32_t*)&l01, *(uint32_t*)&l23);
}

__global__ void __launch_bounds__(256) pmat_kernel(const float* __restrict__ emb,
                                                   const float* __restrict__ Wc,
                                                   const float* __restrict__ bc) {
    extern __shared__ __align__(16) char dsm[];
    uint16_t* sAh = (uint16_t*)dsm;                    // 64*136*2  = 17408 B
    uint16_t* sAl = (uint16_t*)(dsm + 17408);          // 17408 B
    uint16_t* sBh = (uint16_t*)(dsm + 34816);          // 128*136*2 = 34816 B
    uint16_t* sBl = (uint16_t*)(dsm + 69632);          // 34816 B
    __shared__ float s_bias[128];

    const int tid = threadIdx.x;
    const int row0 = blockIdx.x * MT;

    if (tid < 128) s_bias[tid] = bc[tid];

    // ---- A tile: load fp32, split to bf16 hi/lo ----
    #pragma unroll 2
    for (int i = tid; i < MT * 32; i += 256) {         // 32 float4 per row
        int r = i >> 5, q = (i & 31) * 4;
        float4 x = make_float4(0.f, 0.f, 0.f, 0.f);
        if (row0 + r < VOCAB) x = *(const float4*)(emb + (size_t)(row0 + r) * 128 + q);
        split_store(sAh, sAl, r * SAS + q, x);
    }
    // ---- B = W_c: load fp32, split to bf16 hi/lo (per-CTA, L2-cached) ----
    #pragma unroll 4
    for (int i = tid; i < 128 * 32; i += 256) {
        int r = i >> 5, q = (i & 31) * 4;
        float4 w = *(const float4*)(Wc + (size_t)r * 128 + q);
        split_store(sBh, sBl, r * SAS + q, w);
    }
    __syncthreads();

    const int warp = tid >> 5, lane = tid & 31;
    const int grp = lane >> 2, t4 = lane & 3;
    const int quad = lane >> 3, r8 = lane & 7;
    const int m0 = (warp & 1) * 32;
    const int n0 = (warp >> 1) * 32;

    // ldmatrix lane base addresses (bytes).
    // A x4 quads: (m+0..7,k0),(m+8..15,k0),(m+0..7,k+8),(m+8..15,k+8) -> a0..a3
    uint32_t aAh[2], aAl[2];
    #pragma unroll
    for (int mt = 0; mt < 2; mt++) {
        int rowA = m0 + mt * 16 + (quad & 1) * 8 + r8;
        int kA = (quad >> 1) * 8;
        aAh[mt] = su32(sAh) + (rowA * SAS + kA) * 2;
        aAl[mt] = su32(sAl) + (rowA * SAS + kA) * 2;
    }
    // B x4 quads for n16 pair i: (n+0..7,k0),(n+0..7,k+8),(n+8..15,k0),(n+8..15,k+8)
    //   -> b[2i][0], b[2i][1], b[2i+1][0], b[2i+1][1]
    uint32_t aBh[2], aBl[2];
    #pragma unroll
    for (int i = 0; i < 2; i++) {
        int rowB = n0 + i * 16 + (quad >> 1) * 8 + r8;
        int kB = (quad & 1) * 8;
        aBh[i] = su32(sBh) + (rowB * SAS + kB) * 2;
        aBl[i] = su32(sBl) + (rowB * SAS + kB) * 2;
    }

    float acc[2][4][4];
    #pragma unroll
    for (int mt = 0; mt < 2; mt++)
        #pragma unroll
        for (int nt = 0; nt < 4; nt++)
            #pragma unroll
            for (int j = 0; j < 4; j++) acc[mt][nt][j] = 0.f;

    #pragma unroll
    for (int ks = 0; ks < 8; ks++) {
        const uint32_t off = ks * 32;                  // 16 bf16 = 32 B per k-step
        uint32_t ah[2][4], al[2][4];
        LDMX4(ah[0], aAh[0] + off);
        LDMX4(ah[1], aAh[1] + off);
        LDMX4(al[0], aAl[0] + off);
        LDMX4(al[1], aAl[1] + off);
        uint32_t bhp[2][4], blp[2][4];                 // packed: {b[2i][0],b[2i][1],b[2i+1][0],b[2i+1][1]}
        LDMX4(bhp[0], aBh[0] + off);
        LDMX4(bhp[1], aBh[1] + off);
        LDMX4(blp[0], aBl[0] + off);
        LDMX4(blp[1], aBl[1] + off);
        #pragma unroll
        for (int mt = 0; mt < 2; mt++)
            #pragma unroll
            for (int nt = 0; nt < 4; nt++) {
                uint32_t* bh = &bhp[nt >> 1][(nt & 1) * 2];
                uint32_t* bl = &blp[nt >> 1][(nt & 1) * 2];
                MMA16816(acc[mt][nt], ah[mt], bh);
                MMA16816(acc[mt][nt], ah[mt], bl);
                MMA16816(acc[mt][nt], al[mt], bh);
            }
    }

    // ---- epilogue: D + bias -> g_P ----
    #pragma unroll
    for (int mt = 0; mt < 2; mt++) {
        #pragma unroll
        for (int nt = 0; nt < 4; nt++) {
            int col = n0 + nt * 8 + t4 * 2;
            float b0 = s_bias[col], b1 = s_bias[col + 1];
            int r_lo = row0 + m0 + mt * 16 + grp;
            if (r_lo < VOCAB) {
                float2 v = make_float2(acc[mt][nt][0] + b0, acc[mt][nt][1] + b1);
                *(float2*)(g_P + (size_t)r_lo * 128 + col) = v;
            }
            int r_hi = r_lo + 8;
            if (r_hi < VOCAB) {
                float2 v = make_float2(acc[mt][nt][2] + b0, acc[mt][nt][3] + b1);
                *(float2*)(g_P + (size_t)r_hi * 128 + col) = v;
            }
        }
    }
}

// ---------------------------------------------------------------------------
// Kernel B: per (batch, channel-half) CTA: bottom-up subtree sums + max.
//   grid = BS*2, 512 threads. float2 per thread: lane covers ch-pair 2*lane,
//   grp = tid>>5 (0..15) picks nodes. One LDG.64 = full 256 B node row/warp.
// ---------------------------------------------------------------------------
__device__ __forceinline__ float2 f2add(float2 a, float2 b) {
    return make_float2(a.x + b.x, a.y + b.y);
}
__device__ __forceinline__ float2 f2max(float2 a, float2 b) {
    return make_float2(fmaxf(a.x, b.x), fmaxf(a.y, b.y));
}

__global__ void __launch_bounds__(512) tree_kernel(const int* __restrict__ tokens,
                                                   float* __restrict__ out) {
    __shared__ int    stok[1024];        //  4 KB
    __shared__ float2 bufA[64 * 32];     // 16 KB
    __shared__ float2 bufB[32 * 32];     //  8 KB

    const int bh   = blockIdx.x;
    const int b    = bh >> 1;
    const int chb  = (bh & 1) << 6;
    const int tid  = threadIdx.x;
    const int lane = tid & 31;
    const int grp  = tid >> 5;           // 0..15
    const int* tokrow = tokens + (size_t)b * NNODES;

    for (int i = tid; i < NNODES; i += 512) stok[i] = tokrow[i];
    __syncthreads();

    const float2* Pc = (const float2*)(g_P + chb) + lane;  // node t -> Pc[t*64]
    float2 maxv = make_float2(-3.4e38f, -3.4e38f);

    // fused levels 9..6: 64 subtrees rooted at level-6 nodes q = 63+m
    #pragma unroll
    for (int mi = 0; mi < 4; mi++) {
        int m = grp + mi * 16;
        int q = 63 + m;
        int b2 = 2 * q + 1, b4 = 4 * q + 3, b8 = 8 * q + 7;
        float2 v[15];
        v[0] = __ldg(Pc + (size_t)stok[q] * 64);
        #pragma unroll
        for (int j = 0; j < 2; j++) v[1 + j] = __ldg(Pc + (size_t)stok[b2 + j] * 64);
        #pragma unroll
        for (int j = 0; j < 4; j++) v[3 + j] = __ldg(Pc + (size_t)stok[b4 + j] * 64);
        #pragma unroll
        for (int j = 0; j < 8; j++) v[7 + j] = __ldg(Pc + (size_t)stok[b8 + j] * 64);

        float2 s8[4];
        #pragma unroll
        for (int j = 0; j < 4; j++) {
            float2 lft = v[7 + 2 * j], rgt = v[8 + 2 * j];
            maxv = f2max(maxv, f2max(lft, rgt));
            s8[j] = f2add(v[3 + j], f2add(lft, rgt));
            maxv = f2max(maxv, s8[j]);
        }
        float2 s70 = f2add(v[1], f2add(s8[0], s8[1]));
        float2 s71 = f2add(v[2], f2add(s8[2], s8[3]));
        maxv = f2max(maxv, f2max(s70, s71));
        float2 s6 = f2add(v[0], f2add(s70, s71));
        maxv = f2max(maxv, s6);
        bufA[m * 32 + lane] = s6;
    }
    __syncthreads();

    #pragma unroll
    for (int ii = 0; ii < 2; ii++) {             // l5: A(64)->B(32)
        int i = grp + ii * 16;
        float2 v = f2add(f2add(bufA[(2 * i) * 32 + lane], bufA[(2 * i + 1) * 32 + lane]),
                         __ldg(Pc + (size_t)stok[31 + i] * 64));
        maxv = f2max(maxv, v);
        bufB[i * 32 + lane] = v;
    }
    __syncthreads();
    {                                            // l4: B(32)->A(16)
        int i = grp;
        float2 v = f2add(f2add(bufB[(2 * i) * 32 + lane], bufB[(2 * i + 1) * 32 + lane]),
                         __ldg(Pc + (size_t)stok[15 + i] * 64));
        maxv = f2max(maxv, v);
        bufA[i * 32 + lane] = v;
    }
    __syncthreads();
    if (grp < 8) {                               // l3: A(16)->B(8)
        int i = grp;
        float2 v = f2add(f2add(bufA[(2 * i) * 32 + lane], bufA[(2 * i + 1) * 32 + lane]),
                         __ldg(Pc + (size_t)stok[7 + i] * 64));
        maxv = f2max(maxv, v);
        bufB[i * 32 + lane] = v;
    }
    __syncthreads();
    if (grp < 4) {                               // l2: B(8)->A(4)
        int i = grp;
        float2 v = f2add(f2add(bufB[(2 * i) * 32 + lane], bufB[(2 * i + 1) * 32 + lane]),
                         __ldg(Pc + (size_t)stok[3 + i] * 64));
        maxv = f2max(maxv, v);
        bufA[i * 32 + lane] = v;
    }
    __syncthreads();
    if (grp < 2) {                               // l1: A(4)->B(2)
        int i = grp;
        float2 v = f2add(f2add(bufA[(2 * i) * 32 + lane], bufA[(2 * i + 1) * 32 + lane]),
                         __ldg(Pc + (size_t)stok[1 + i] * 64));
        maxv = f2max(maxv, v);
        bufB[i * 32 + lane] = v;
    }
    __syncthreads();
    if (grp == 0) {                              // l0: root
        float2 v = f2add(f2add(bufB[lane], bufB[32 + lane]),
                         __ldg(Pc + (size_t)stok[0] * 64));
        maxv = f2max(maxv, v);
    }

    // cross-group max (reuse bufA: [grp][lane])
    bufA[grp * 32 + lane] = maxv;
    __syncthreads();
    if (grp == 0) {
        float2 m = bufA[lane];
        #pragma unroll
        for (int g = 1; g < 16; g++) m = f2max(m, bufA[g * 32 + lane]);
        *(float2*)(out + (size_t)b * 128 + chb + 2 * lane) = m;
    }
}

// ---------------------------------------------------------------------------
// kernel_launch
// ---------------------------------------------------------------------------
extern "C" void kernel_launch(void* const* d_in, const int* in_sizes, int n_in,
                              void* d_out, int out_size) {
    const int*   tokens = (const int*)d_in[0];
    const float* emb    = (const float*)d_in[1];
    const float* Wc     = (const float*)d_in[2];
    const float* bc     = (const float*)d_in[3];
    float*       out    = (float*)d_out;

    const int smemA = 2 * 17408 + 2 * 34816;   // 104448 B
    cudaFuncSetAttribute(pmat_kernel, cudaFuncAttributeMaxDynamicSharedMemorySize, smemA);

    const int gridA = (VOCAB + MT - 1) / MT;   // 469
    pmat_kernel<<<gridA, 256, smemA>>>(emb, Wc, bc);
    tree_kernel<<<BS * 2, 512>>>(tokens, out);
}

// round 8
// speedup vs baseline: 3.8520x; 1.0011x over previous
#include <cuda_runtime.h>
#include <cuda_bf16.h>
#include <cuda_fp16.h>
#include <cstdint>

#define VOCAB 30000
#define EMB 128
#define ENC 128
#define BS 256
#define NNODES 1023

// Precomputed P[t][o] = dot(emb[t,:], W_c[o,:]) + b_c[o], stored fp16 (7.7 MB).
// fp16 rounding: ~2.4e-5 abs per element -> ~2e-4 rel on outputs (thr 1e-3).
__device__ __half g_Ph[VOCAB * ENC];

// ---------------------------------------------------------------------------
// Kernel A: P = emb @ W_c^T + b_c via mma.sync m16n8k16 bf16 (HMMA),
// split-precision: emb=eh+el, W=wh+wl, D = eh*wh + eh*wl + el*wh (fp32 acc).
//   CTA: 256 thr (8 warps), tile M=64 x N=128 x K=128.
//   Fragments via ldmatrix.x4. Epilogue stores fp16.
// ---------------------------------------------------------------------------
#define MT 64
#define SAS 136   // smem row stride in bf16 elements (272 B: ldmatrix conflict-free)

#define MMA16816(c, a, b)                                                   \
    asm("mma.sync.aligned.m16n8k16.row.col.f32.bf16.bf16.f32 "              \
        "{%0,%1,%2,%3}, {%4,%5,%6,%7}, {%8,%9}, {%0,%1,%2,%3};"             \
        : "+f"((c)[0]), "+f"((c)[1]), "+f"((c)[2]), "+f"((c)[3])            \
        : "r"((a)[0]), "r"((a)[1]), "r"((a)[2]), "r"((a)[3]),               \
          "r"((b)[0]), "r"((b)[1]))

#define LDMX4(r, addr)                                                      \
    asm volatile("ldmatrix.sync.aligned.m8n8.x4.shared.b16 "                \
                 "{%0,%1,%2,%3}, [%4];"                                     \
                 : "=r"((r)[0]), "=r"((r)[1]), "=r"((r)[2]), "=r"((r)[3])   \
                 : "r"(addr))

__device__ __forceinline__ uint32_t su32(const void* p) {
    return (uint32_t)__cvta_generic_to_shared(p);
}

__device__ __forceinline__ void split_store(uint16_t* __restrict__ h,
                                            uint16_t* __restrict__ l,
                                            int off, float4 x) {
    __nv_bfloat162 h01 = __floats2bfloat162_rn(x.x, x.y);
    __nv_bfloat162 h23 = __floats2bfloat162_rn(x.z, x.w);
    __nv_bfloat162 l01 = __floats2bfloat162_rn(x.x - __bfloat162float(h01.x),
                                               x.y - __bfloat162float(h01.y));
    __nv_bfloat162 l23 = __floats2bfloat162_rn(x.z - __bfloat162float(h23.x),
                                               x.w - __bfloat162float(h23.y));
    *(uint2*)(h + off) = make_uint2(*(uint32_t*)&h01, *(uint32_t*)&h23);
    *(uint2*)(l + off) = make_uint2(*(uint32_t*)&l01, *(uint32_t*)&l23);
}

__global__ void __launch_bounds__(256) pmat_kernel(const float* __restrict__ emb,
                                                   const float* __restrict__ Wc,
                                                   const float* __restrict__ bc) {
    extern __shared__ __align__(16) char dsm[];
    uint16_t* sAh = (uint16_t*)dsm;                    // 64*136*2  = 17408 B
    uint16_t* sAl = (uint16_t*)(dsm + 17408);          // 17408 B
    uint16_t* sBh = (uint16_t*)(dsm + 34816);          // 128*136*2 = 34816 B
    uint16_t* sBl = (uint16_t*)(dsm + 69632);          // 34816 B
    __shared__ float s_bias[128];

    const int tid = threadIdx.x;
    const int row0 = blockIdx.x * MT;

    if (tid < 128) s_bias[tid] = bc[tid];

    // ---- A tile: load fp32, split to bf16 hi/lo ----
    #pragma unroll 2
    for (int i = tid; i < MT * 32; i += 256) {         // 32 float4 per row
        int r = i >> 5, q = (i & 31) * 4;
        float4 x = make_float4(0.f, 0.f, 0.f, 0.f);
        if (row0 + r < VOCAB) x = *(const float4*)(emb + (size_t)(row0 + r) * 128 + q);
        split_store(sAh, sAl, r * SAS + q, x);
    }
    // ---- B = W_c: load fp32, split to bf16 hi/lo (per-CTA, L2-cached) ----
    #pragma unroll 4
    for (int i = tid; i < 128 * 32; i += 256) {
        int r = i >> 5, q = (i & 31) * 4;
        float4 w = *(const float4*)(Wc + (size_t)r * 128 + q);
        split_store(sBh, sBl, r * SAS + q, w);
    }
    __syncthreads();

    const int warp = tid >> 5, lane = tid & 31;
    const int grp = lane >> 2, t4 = lane & 3;
    const int quad = lane >> 3, r8 = lane & 7;
    const int m0 = (warp & 1) * 32;
    const int n0 = (warp >> 1) * 32;

    // ldmatrix lane base addresses (bytes).
    uint32_t aAh[2], aAl[2];
    #pragma unroll
    for (int mt = 0; mt < 2; mt++) {
        int rowA = m0 + mt * 16 + (quad & 1) * 8 + r8;
        int kA = (quad >> 1) * 8;
        aAh[mt] = su32(sAh) + (rowA * SAS + kA) * 2;
        aAl[mt] = su32(sAl) + (rowA * SAS + kA) * 2;
    }
    uint32_t aBh[2], aBl[2];
    #pragma unroll
    for (int i = 0; i < 2; i++) {
        int rowB = n0 + i * 16 + (quad >> 1) * 8 + r8;
        int kB = (quad & 1) * 8;
        aBh[i] = su32(sBh) + (rowB * SAS + kB) * 2;
        aBl[i] = su32(sBl) + (rowB * SAS + kB) * 2;
    }

    float acc[2][4][4];
    #pragma unroll
    for (int mt = 0; mt < 2; mt++)
        #pragma unroll
        for (int nt = 0; nt < 4; nt++)
            #pragma unroll
            for (int j = 0; j < 4; j++) acc[mt][nt][j] = 0.f;

    #pragma unroll
    for (int ks = 0; ks < 8; ks++) {
        const uint32_t off = ks * 32;                  // 16 bf16 = 32 B per k-step
        uint32_t ah[2][4], al[2][4];
        LDMX4(ah[0], aAh[0] + off);
        LDMX4(ah[1], aAh[1] + off);
        LDMX4(al[0], aAl[0] + off);
        LDMX4(al[1], aAl[1] + off);
        uint32_t bhp[2][4], blp[2][4];
        LDMX4(bhp[0], aBh[0] + off);
        LDMX4(bhp[1], aBh[1] + off);
        LDMX4(blp[0], aBl[0] + off);
        LDMX4(blp[1], aBl[1] + off);
        #pragma unroll
        for (int mt = 0; mt < 2; mt++)
            #pragma unroll
            for (int nt = 0; nt < 4; nt++) {
                uint32_t* bh = &bhp[nt >> 1][(nt & 1) * 2];
                uint32_t* bl = &blp[nt >> 1][(nt & 1) * 2];
                MMA16816(acc[mt][nt], ah[mt], bh);
                MMA16816(acc[mt][nt], ah[mt], bl);
                MMA16816(acc[mt][nt], al[mt], bh);
            }
    }

    // ---- epilogue: (D + bias) -> fp16 -> g_Ph ----
    #pragma unroll
    for (int mt = 0; mt < 2; mt++) {
        #pragma unroll
        for (int nt = 0; nt < 4; nt++) {
            int col = n0 + nt * 8 + t4 * 2;
            float b0 = s_bias[col], b1 = s_bias[col + 1];
            int r_lo = row0 + m0 + mt * 16 + grp;
            if (r_lo < VOCAB) {
                __half2 v = __floats2half2_rn(acc[mt][nt][0] + b0, acc[mt][nt][1] + b1);
                *(__half2*)(g_Ph + (size_t)r_lo * 128 + col) = v;
            }
            int r_hi = r_lo + 8;
            if (r_hi < VOCAB) {
                __half2 v = __floats2half2_rn(acc[mt][nt][2] + b0, acc[mt][nt][3] + b1);
                *(__half2*)(g_Ph + (size_t)r_hi * 128 + col) = v;
            }
        }
    }
}

// ---------------------------------------------------------------------------
// Kernel B: per (batch, channel-half) CTA: bottom-up subtree sums + max.
//   grid = BS*2, 512 threads. Lane covers ch-pair via one half2 LDG.32
//   (128 B/warp = 4 sectors, half the LSU wavefronts of fp32 float2).
//   All sums/max in fp32.
// ---------------------------------------------------------------------------
__device__ __forceinline__ float2 f2add(float2 a, float2 b) {
    return make_float2(a.x + b.x, a.y + b.y);
}
__device__ __forceinline__ float2 f2max(float2 a, float2 b) {
    return make_float2(fmaxf(a.x, b.x), fmaxf(a.y, b.y));
}
__device__ __forceinline__ float2 ldP(const uint32_t* p) {
    uint32_t u = __ldg(p);
    return __half22float2(*(__half2*)&u);
}

__global__ void __launch_bounds__(512) tree_kernel(const int* __restrict__ tokens,
                                                   float* __restrict__ out) {
    __shared__ int    stok[1024];        //  4 KB
    __shared__ float2 bufA[64 * 32];     // 16 KB
    __shared__ float2 bufB[32 * 32];     //  8 KB

    const int bh   = blockIdx.x;
    const int b    = bh >> 1;
    const int chb  = (bh & 1) << 6;
    const int tid  = threadIdx.x;
    const int lane = tid & 31;
    const int grp  = tid >> 5;           // 0..15
    const int* tokrow = tokens + (size_t)b * NNODES;

    for (int i = tid; i < NNODES; i += 512) stok[i] = tokrow[i];
    __syncthreads();

    // node t -> Pc[t*64]; each uint32 = half2 = 2 channels
    const uint32_t* Pc = (const uint32_t*)g_Ph + (chb >> 1) + lane;
    float2 maxv = make_float2(-3.4e38f, -3.4e38f);

    // fused levels 9..6: 64 subtrees rooted at level-6 nodes q = 63+m
    #pragma unroll
    for (int mi = 0; mi < 4; mi++) {
        int m = grp + mi * 16;
        int q = 63 + m;
        int b2 = 2 * q + 1, b4 = 4 * q + 3, b8 = 8 * q + 7;
        float2 v[15];
        v[0] = ldP(Pc + (size_t)stok[q] * 64);
        #pragma unroll
        for (int j = 0; j < 2; j++) v[1 + j] = ldP(Pc + (size_t)stok[b2 + j] * 64);
        #pragma unroll
        for (int j = 0; j < 4; j++) v[3 + j] = ldP(Pc + (size_t)stok[b4 + j] * 64);
        #pragma unroll
        for (int j = 0; j < 8; j++) v[7 + j] = ldP(Pc + (size_t)stok[b8 + j] * 64);

        float2 s8[4];
        #pragma unroll
        for (int j = 0; j < 4; j++) {
            float2 lft = v[7 + 2 * j], rgt = v[8 + 2 * j];
            maxv = f2max(maxv, f2max(lft, rgt));
            s8[j] = f2add(v[3 + j], f2add(lft, rgt));
            maxv = f2max(maxv, s8[j]);
        }
        float2 s70 = f2add(v[1], f2add(s8[0], s8[1]));
        float2 s71 = f2add(v[2], f2add(s8[2], s8[3]));
        maxv = f2max(maxv, f2max(s70, s71));
        float2 s6 = f2add(v[0], f2add(s70, s71));
        maxv = f2max(maxv, s6);
        bufA[m * 32 + lane] = s6;
    }
    __syncthreads();

    #pragma unroll
    for (int ii = 0; ii < 2; ii++) {             // l5: A(64)->B(32)
        int i = grp + ii * 16;
        float2 v = f2add(f2add(bufA[(2 * i) * 32 + lane], bufA[(2 * i + 1) * 32 + lane]),
                         ldP(Pc + (size_t)stok[31 + i] * 64));
        maxv = f2max(maxv, v);
        bufB[i * 32 + lane] = v;
    }
    __syncthreads();
    {                                            // l4: B(32)->A(16)
        int i = grp;
        float2 v = f2add(f2add(bufB[(2 * i) * 32 + lane], bufB[(2 * i + 1) * 32 + lane]),
                         ldP(Pc + (size_t)stok[15 + i] * 64));
        maxv = f2max(maxv, v);
        bufA[i * 32 + lane] = v;
    }
    __syncthreads();
    if (grp < 8) {                               // l3: A(16)->B(8)
        int i = grp;
        float2 v = f2add(f2add(bufA[(2 * i) * 32 + lane], bufA[(2 * i + 1) * 32 + lane]),
                         ldP(Pc + (size_t)stok[7 + i] * 64));
        maxv = f2max(maxv, v);
        bufB[i * 32 + lane] = v;
    }
    __syncthreads();
    if (grp < 4) {                               // l2: B(8)->A(4)
        int i = grp;
        float2 v = f2add(f2add(bufB[(2 * i) * 32 + lane], bufB[(2 * i + 1) * 32 + lane]),
                         ldP(Pc + (size_t)stok[3 + i] * 64));
        maxv = f2max(maxv, v);
        bufA[i * 32 + lane] = v;
    }
    __syncthreads();
    if (grp < 2) {                               // l1: A(4)->B(2)
        int i = grp;
        float2 v = f2add(f2add(bufA[(2 * i) * 32 + lane], bufA[(2 * i + 1) * 32 + lane]),
                         ldP(Pc + (size_t)stok[1 + i] * 64));
        maxv = f2max(maxv, v);
        bufB[i * 32 + lane] = v;
    }
    __syncthreads();
    if (grp == 0) {                              // l0: root
        float2 v = f2add(f2add(bufB[lane], bufB[32 + lane]),
                         ldP(Pc + (size_t)stok[0] * 64));
        maxv = f2max(maxv, v);
    }

    // cross-group max (reuse bufA: [grp][lane])
    bufA[grp * 32 + lane] = maxv;
    __syncthreads();
    if (grp == 0) {
        float2 m = bufA[lane];
        #pragma unroll
        for (int g = 1; g < 16; g++) m = f2max(m, bufA[g * 32 + lane]);
        *(float2*)(out + (size_t)b * 128 + chb + 2 * lane) = m;
    }
}

// ---------------------------------------------------------------------------
// kernel_launch
// ---------------------------------------------------------------------------
extern "C" void kernel_launch(void* const* d_in, const int* in_sizes, int n_in,
                              void* d_out, int out_size) {
    const int*   tokens = (const int*)d_in[0];
    const float* emb    = (const float*)d_in[1];
    const float* Wc     = (const float*)d_in[2];
    const float* bc     = (const float*)d_in[3];
    float*       out    = (float*)d_out;

    const int smemA = 2 * 17408 + 2 * 34816;   // 104448 B
    cudaFuncSetAttribute(pmat_kernel, cudaFuncAttributeMaxDynamicSharedMemorySize, smemA);

    const int gridA = (VOCAB + MT - 1) / MT;   // 469
    pmat_kernel<<<gridA, 256, smemA>>>(emb, Wc, bc);
    tree_kernel<<<BS * 2, 512>>>(tokens, out);
}

// round 9
// speedup vs baseline: 4.5269x; 1.1752x over previous
#include <cuda_runtime.h>
#include <cuda_fp16.h>
#include <cstdint>

#define VOCAB 30000
#define EMB 128
#define ENC 128
#define BS 256
#define NNODES 1023

// Precomputed P[t][o] = dot(emb[t,:], W_c[o,:]) + b_c[o], stored fp16 (7.7 MB).
__device__ __half g_Ph[VOCAB * ENC];

// ---------------------------------------------------------------------------
// Kernel A: P = emb @ W_c^T + b_c via mma.sync m16n8k16 fp16 (HMMA, fp32 acc).
//   Pure fp16 inputs (single term). Calibrated on R8 measurement: each 2^-11
//   error source adds ~1.5e-5 final rel_err -> predicted ~1e-4 (thr 1e-3).
//   CTA: 256 thr (8 warps), tile M=64 x N=128 x K=128, smem 52 KB -> 4 CTA/SM
//   -> grid 469 fits in ONE wave (592 resident slots).
// ---------------------------------------------------------------------------
#define MT 64
#define SAS 136   // smem row stride in fp16 elements (272 B: ldmatrix conflict-free)

#define MMA16816(c, a, b)                                                   \
    asm("mma.sync.aligned.m16n8k16.row.col.f32.f16.f16.f32 "                \
        "{%0,%1,%2,%3}, {%4,%5,%6,%7}, {%8,%9}, {%0,%1,%2,%3};"             \
        : "+f"((c)[0]), "+f"((c)[1]), "+f"((c)[2]), "+f"((c)[3])            \
        : "r"((a)[0]), "r"((a)[1]), "r"((a)[2]), "r"((a)[3]),               \
          "r"((b)[0]), "r"((b)[1]))

#define LDMX4(r, addr)                                                      \
    asm volatile("ldmatrix.sync.aligned.m8n8.x4.shared.b16 "                \
                 "{%0,%1,%2,%3}, [%4];"                                     \
                 : "=r"((r)[0]), "=r"((r)[1]), "=r"((r)[2]), "=r"((r)[3])   \
                 : "r"(addr))

__device__ __forceinline__ uint32_t su32(const void* p) {
    return (uint32_t)__cvta_generic_to_shared(p);
}

// fp32x4 -> fp16x4 (one uint2 store)
__device__ __forceinline__ void cvt_store(uint16_t* __restrict__ dst, int off, float4 x) {
    __half2 p01 = __floats2half2_rn(x.x, x.y);
    __half2 p23 = __floats2half2_rn(x.z, x.w);
    *(uint2*)(dst + off) = make_uint2(*(uint32_t*)&p01, *(uint32_t*)&p23);
}

__global__ void __launch_bounds__(256) pmat_kernel(const float* __restrict__ emb,
                                                   const float* __restrict__ Wc,
                                                   const float* __restrict__ bc) {
    extern __shared__ __align__(16) char dsm[];
    uint16_t* sA = (uint16_t*)dsm;                     // 64*136*2  = 17408 B
    uint16_t* sB = (uint16_t*)(dsm + 17408);           // 128*136*2 = 34816 B
    __shared__ float s_bias[128];

    const int tid = threadIdx.x;
    const int row0 = blockIdx.x * MT;

    if (tid < 128) s_bias[tid] = bc[tid];

    // ---- A tile: load fp32, convert fp16 ----
    #pragma unroll 2
    for (int i = tid; i < MT * 32; i += 256) {         // 32 float4 per row
        int r = i >> 5, q = (i & 31) * 4;
        float4 x = make_float4(0.f, 0.f, 0.f, 0.f);
        if (row0 + r < VOCAB) x = *(const float4*)(emb + (size_t)(row0 + r) * 128 + q);
        cvt_store(sA, r * SAS + q, x);
    }
    // ---- B = W_c: load fp32, convert fp16 (per-CTA, L2-cached) ----
    #pragma unroll 4
    for (int i = tid; i < 128 * 32; i += 256) {
        int r = i >> 5, q = (i & 31) * 4;
        float4 w = *(const float4*)(Wc + (size_t)r * 128 + q);
        cvt_store(sB, r * SAS + q, w);
    }
    __syncthreads();

    const int warp = tid >> 5, lane = tid & 31;
    const int grp = lane >> 2, t4 = lane & 3;
    const int quad = lane >> 3, r8 = lane & 7;
    const int m0 = (warp & 1) * 32;
    const int n0 = (warp >> 1) * 32;

    // ldmatrix lane base addresses (bytes).
    uint32_t aA[2];
    #pragma unroll
    for (int mt = 0; mt < 2; mt++) {
        int rowA = m0 + mt * 16 + (quad & 1) * 8 + r8;
        int kA = (quad >> 1) * 8;
        aA[mt] = su32(sA) + (rowA * SAS + kA) * 2;
    }
    uint32_t aB[2];
    #pragma unroll
    for (int i = 0; i < 2; i++) {
        int rowB = n0 + i * 16 + (quad >> 1) * 8 + r8;
        int kB = (quad & 1) * 8;
        aB[i] = su32(sB) + (rowB * SAS + kB) * 2;
    }

    float acc[2][4][4];
    #pragma unroll
    for (int mt = 0; mt < 2; mt++)
        #pragma unroll
        for (int nt = 0; nt < 4; nt++)
            #pragma unroll
            for (int j = 0; j < 4; j++) acc[mt][nt][j] = 0.f;

    #pragma unroll
    for (int ks = 0; ks < 8; ks++) {
        const uint32_t off = ks * 32;                  // 16 fp16 = 32 B per k-step
        uint32_t a[2][4];
        LDMX4(a[0], aA[0] + off);
        LDMX4(a[1], aA[1] + off);
        uint32_t bp[2][4];   // packed: {b[2i][0],b[2i][1],b[2i+1][0],b[2i+1][1]}
        LDMX4(bp[0], aB[0] + off);
        LDMX4(bp[1], aB[1] + off);
        #pragma unroll
        for (int mt = 0; mt < 2; mt++)
            #pragma unroll
            for (int nt = 0; nt < 4; nt++) {
                uint32_t* bb = &bp[nt >> 1][(nt & 1) * 2];
                MMA16816(acc[mt][nt], a[mt], bb);
            }
    }

    // ---- epilogue: (D + bias) -> fp16 -> g_Ph ----
    #pragma unroll
    for (int mt = 0; mt < 2; mt++) {
        #pragma unroll
        for (int nt = 0; nt < 4; nt++) {
            int col = n0 + nt * 8 + t4 * 2;
            float b0 = s_bias[col], b1 = s_bias[col + 1];
            int r_lo = row0 + m0 + mt * 16 + grp;
            if (r_lo < VOCAB) {
                __half2 v = __floats2half2_rn(acc[mt][nt][0] + b0, acc[mt][nt][1] + b1);
                *(__half2*)(g_Ph + (size_t)r_lo * 128 + col) = v;
            }
            int r_hi = r_lo + 8;
            if (r_hi < VOCAB) {
                __half2 v = __floats2half2_rn(acc[mt][nt][2] + b0, acc[mt][nt][3] + b1);
                *(__half2*)(g_Ph + (size_t)r_hi * 128 + col) = v;
            }
        }
    }
}

// ---------------------------------------------------------------------------
// Kernel B: per (batch, channel-half) CTA: bottom-up subtree sums + max.
//   grid = BS*2, 512 threads. Lane covers ch-pair via one half2 LDG.32.
//   All sums/max in fp32. (Unchanged from R8.)
// ---------------------------------------------------------------------------
__device__ __forceinline__ float2 f2add(float2 a, float2 b) {
    return make_float2(a.x + b.x, a.y + b.y);
}
__device__ __forceinline__ float2 f2max(float2 a, float2 b) {
    return make_float2(fmaxf(a.x, b.x), fmaxf(a.y, b.y));
}
__device__ __forceinline__ float2 ldP(const uint32_t* p) {
    uint32_t u = __ldg(p);
    return __half22float2(*(__half2*)&u);
}

__global__ void __launch_bounds__(512) tree_kernel(const int* __restrict__ tokens,
                                                   float* __restrict__ out) {
    __shared__ int    stok[1024];        //  4 KB
    __shared__ float2 bufA[64 * 32];     // 16 KB
    __shared__ float2 bufB[32 * 32];     //  8 KB

    const int bh   = blockIdx.x;
    const int b    = bh >> 1;
    const int chb  = (bh & 1) << 6;
    const int tid  = threadIdx.x;
    const int lane = tid & 31;
    const int grp  = tid >> 5;           // 0..15
    const int* tokrow = tokens + (size_t)b * NNODES;

    for (int i = tid; i < NNODES; i += 512) stok[i] = tokrow[i];
    __syncthreads();

    // node t -> Pc[t*64]; each uint32 = half2 = 2 channels
    const uint32_t* Pc = (const uint32_t*)g_Ph + (chb >> 1) + lane;
    float2 maxv = make_float2(-3.4e38f, -3.4e38f);

    // fused levels 9..6: 64 subtrees rooted at level-6 nodes q = 63+m
    #pragma unroll
    for (int mi = 0; mi < 4; mi++) {
        int m = grp + mi * 16;
        int q = 63 + m;
        int b2 = 2 * q + 1, b4 = 4 * q + 3, b8 = 8 * q + 7;
        float2 v[15];
        v[0] = ldP(Pc + (size_t)stok[q] * 64);
        #pragma unroll
        for (int j = 0; j < 2; j++) v[1 + j] = ldP(Pc + (size_t)stok[b2 + j] * 64);
        #pragma unroll
        for (int j = 0; j < 4; j++) v[3 + j] = ldP(Pc + (size_t)stok[b4 + j] * 64);
        #pragma unroll
        for (int j = 0; j < 8; j++) v[7 + j] = ldP(Pc + (size_t)stok[b8 + j] * 64);

        float2 s8[4];
        #pragma unroll
        for (int j = 0; j < 4; j++) {
            float2 lft = v[7 + 2 * j], rgt = v[8 + 2 * j];
            maxv = f2max(maxv, f2max(lft, rgt));
            s8[j] = f2add(v[3 + j], f2add(lft, rgt));
            maxv = f2max(maxv, s8[j]);
        }
        float2 s70 = f2add(v[1], f2add(s8[0], s8[1]));
        float2 s71 = f2add(v[2], f2add(s8[2], s8[3]));
        maxv = f2max(maxv, f2max(s70, s71));
        float2 s6 = f2add(v[0], f2add(s70, s71));
        maxv = f2max(maxv, s6);
        bufA[m * 32 + lane] = s6;
    }
    __syncthreads();

    #pragma unroll
    for (int ii = 0; ii < 2; ii++) {             // l5: A(64)->B(32)
        int i = grp + ii * 16;
        float2 v = f2add(f2add(bufA[(2 * i) * 32 + lane], bufA[(2 * i + 1) * 32 + lane]),
                         ldP(Pc + (size_t)stok[31 + i] * 64));
        maxv = f2max(maxv, v);
        bufB[i * 32 + lane] = v;
    }
    __syncthreads();
    {                                            // l4: B(32)->A(16)
        int i = grp;
        float2 v = f2add(f2add(bufB[(2 * i) * 32 + lane], bufB[(2 * i + 1) * 32 + lane]),
                         ldP(Pc + (size_t)stok[15 + i] * 64));
        maxv = f2max(maxv, v);
        bufA[i * 32 + lane] = v;
    }
    __syncthreads();
    if (grp < 8) {                               // l3: A(16)->B(8)
        int i = grp;
        float2 v = f2add(f2add(bufA[(2 * i) * 32 + lane], bufA[(2 * i + 1) * 32 + lane]),
                         ldP(Pc + (size_t)stok[7 + i] * 64));
        maxv = f2max(maxv, v);
        bufB[i * 32 + lane] = v;
    }
    __syncthreads();
    if (grp < 4) {                               // l2: B(8)->A(4)
        int i = grp;
        float2 v = f2add(f2add(bufB[(2 * i) * 32 + lane], bufB[(2 * i + 1) * 32 + lane]),
                         ldP(Pc + (size_t)stok[3 + i] * 64));
        maxv = f2max(maxv, v);
        bufA[i * 32 + lane] = v;
    }
    __syncthreads();
    if (grp < 2) {                               // l1: A(4)->B(2)
        int i = grp;
        float2 v = f2add(f2add(bufA[(2 * i) * 32 + lane], bufA[(2 * i + 1) * 32 + lane]),
                         ldP(Pc + (size_t)stok[1 + i] * 64));
        maxv = f2max(maxv, v);
        bufB[i * 32 + lane] = v;
    }
    __syncthreads();
    if (grp == 0) {                              // l0: root
        float2 v = f2add(f2add(bufB[lane], bufB[32 + lane]),
                         ldP(Pc + (size_t)stok[0] * 64));
        maxv = f2max(maxv, v);
    }

    // cross-group max (reuse bufA: [grp][lane])
    bufA[grp * 32 + lane] = maxv;
    __syncthreads();
    if (grp == 0) {
        float2 m = bufA[lane];
        #pragma unroll
        for (int g = 1; g < 16; g++) m = f2max(m, bufA[g * 32 + lane]);
        *(float2*)(out + (size_t)b * 128 + chb + 2 * lane) = m;
    }
}

// ---------------------------------------------------------------------------
// kernel_launch
// ---------------------------------------------------------------------------
extern "C" void kernel_launch(void* const* d_in, const int* in_sizes, int n_in,
                              void* d_out, int out_size) {
    const int*   tokens = (const int*)d_in[0];
    const float* emb    = (const float*)d_in[1];
    const float* Wc     = (const float*)d_in[2];
    const float* bc     = (const float*)d_in[3];
    float*       out    = (float*)d_out;

    const int smemA = 17408 + 34816;   // 52224 B -> 4 CTAs/SM
    cudaFuncSetAttribute(pmat_kernel, cudaFuncAttributeMaxDynamicSharedMemorySize, smemA);

    const int gridA = (VOCAB + MT - 1) / MT;   // 469
    pmat_kernel<<<gridA, 256, smemA>>>(emb, Wc, bc);
    tree_kernel<<<BS * 2, 512>>>(tokens, out);
}

// round 10
// speedup vs baseline: 4.8693x; 1.0757x over previous
#include <cuda_runtime.h>
#include <cuda_fp16.h>
#include <cstdint>

#define VOCAB 30000
#define EMB 128
#define ENC 128
#define BS 256
#define NNODES 1023

// Precomputed P[t][o] = dot(emb[t,:], W_c[o,:]) + b_c[o], stored fp16 (7.7 MB).
__device__ __half g_Ph[VOCAB * ENC];

// ---------------------------------------------------------------------------
// Kernel A: P = emb @ W_c^T + b_c via mma.sync m16n8k16 fp16 (HMMA, fp32 acc).
//   (unchanged from R9: 469 CTAs x 256 thr, 52 KB smem, 4 CTA/SM, one wave)
// ---------------------------------------------------------------------------
#define MT 64
#define SAS 136   // smem row stride in fp16 elements (272 B: ldmatrix conflict-free)

#define MMA16816(c, a, b)                                                   \
    asm("mma.sync.aligned.m16n8k16.row.col.f32.f16.f16.f32 "                \
        "{%0,%1,%2,%3}, {%4,%5,%6,%7}, {%8,%9}, {%0,%1,%2,%3};"             \
        : "+f"((c)[0]), "+f"((c)[1]), "+f"((c)[2]), "+f"((c)[3])            \
        : "r"((a)[0]), "r"((a)[1]), "r"((a)[2]), "r"((a)[3]),               \
          "r"((b)[0]), "r"((b)[1]))

#define LDMX4(r, addr)                                                      \
    asm volatile("ldmatrix.sync.aligned.m8n8.x4.shared.b16 "                \
                 "{%0,%1,%2,%3}, [%4];"                                     \
                 : "=r"((r)[0]), "=r"((r)[1]), "=r"((r)[2]), "=r"((r)[3])   \
                 : "r"(addr))

__device__ __forceinline__ uint32_t su32(const void* p) {
    return (uint32_t)__cvta_generic_to_shared(p);
}

__device__ __forceinline__ void cvt_store(uint16_t* __restrict__ dst, int off, float4 x) {
    __half2 p01 = __floats2half2_rn(x.x, x.y);
    __half2 p23 = __floats2half2_rn(x.z, x.w);
    *(uint2*)(dst + off) = make_uint2(*(uint32_t*)&p01, *(uint32_t*)&p23);
}

__global__ void __launch_bounds__(256) pmat_kernel(const float* __restrict__ emb,
                                                   const float* __restrict__ Wc,
                                                   const float* __restrict__ bc) {
    extern __shared__ __align__(16) char dsm[];
    uint16_t* sA = (uint16_t*)dsm;                     // 64*136*2  = 17408 B
    uint16_t* sB = (uint16_t*)(dsm + 17408);           // 128*136*2 = 34816 B
    __shared__ float s_bias[128];

    const int tid = threadIdx.x;
    const int row0 = blockIdx.x * MT;

    if (tid < 128) s_bias[tid] = bc[tid];

    #pragma unroll 2
    for (int i = tid; i < MT * 32; i += 256) {
        int r = i >> 5, q = (i & 31) * 4;
        float4 x = make_float4(0.f, 0.f, 0.f, 0.f);
        if (row0 + r < VOCAB) x = *(const float4*)(emb + (size_t)(row0 + r) * 128 + q);
        cvt_store(sA, r * SAS + q, x);
    }
    #pragma unroll 4
    for (int i = tid; i < 128 * 32; i += 256) {
        int r = i >> 5, q = (i & 31) * 4;
        float4 w = *(const float4*)(Wc + (size_t)r * 128 + q);
        cvt_store(sB, r * SAS + q, w);
    }
    __syncthreads();

    const int warp = tid >> 5, lane = tid & 31;
    const int grp = lane >> 2, t4 = lane & 3;
    const int quad = lane >> 3, r8 = lane & 7;
    const int m0 = (warp & 1) * 32;
    const int n0 = (warp >> 1) * 32;

    uint32_t aA[2];
    #pragma unroll
    for (int mt = 0; mt < 2; mt++) {
        int rowA = m0 + mt * 16 + (quad & 1) * 8 + r8;
        int kA = (quad >> 1) * 8;
        aA[mt] = su32(sA) + (rowA * SAS + kA) * 2;
    }
    uint32_t aB[2];
    #pragma unroll
    for (int i = 0; i < 2; i++) {
        int rowB = n0 + i * 16 + (quad >> 1) * 8 + r8;
        int kB = (quad & 1) * 8;
        aB[i] = su32(sB) + (rowB * SAS + kB) * 2;
    }

    float acc[2][4][4];
    #pragma unroll
    for (int mt = 0; mt < 2; mt++)
        #pragma unroll
        for (int nt = 0; nt < 4; nt++)
            #pragma unroll
            for (int j = 0; j < 4; j++) acc[mt][nt][j] = 0.f;

    #pragma unroll
    for (int ks = 0; ks < 8; ks++) {
        const uint32_t off = ks * 32;
        uint32_t a[2][4];
        LDMX4(a[0], aA[0] + off);
        LDMX4(a[1], aA[1] + off);
        uint32_t bp[2][4];
        LDMX4(bp[0], aB[0] + off);
        LDMX4(bp[1], aB[1] + off);
        #pragma unroll
        for (int mt = 0; mt < 2; mt++)
            #pragma unroll
            for (int nt = 0; nt < 4; nt++) {
                uint32_t* bb = &bp[nt >> 1][(nt & 1) * 2];
                MMA16816(acc[mt][nt], a[mt], bb);
            }
    }

    #pragma unroll
    for (int mt = 0; mt < 2; mt++) {
        #pragma unroll
        for (int nt = 0; nt < 4; nt++) {
            int col = n0 + nt * 8 + t4 * 2;
            float b0 = s_bias[col], b1 = s_bias[col + 1];
            int r_lo = row0 + m0 + mt * 16 + grp;
            if (r_lo < VOCAB) {
                __half2 v = __floats2half2_rn(acc[mt][nt][0] + b0, acc[mt][nt][1] + b1);
                *(__half2*)(g_Ph + (size_t)r_lo * 128 + col) = v;
            }
            int r_hi = r_lo + 8;
            if (r_hi < VOCAB) {
                __half2 v = __floats2half2_rn(acc[mt][nt][2] + b0, acc[mt][nt][3] + b1);
                *(__half2*)(g_Ph + (size_t)r_hi * 128 + col) = v;
            }
        }
    }
}

// ---------------------------------------------------------------------------
// Kernel B: per (batch, channel-half) CTA: bottom-up subtree sums + max.
//   Levels 9+8 computed in fp16 (HADD2/HMNMX2) directly on gathered half2;
//   level-8 sums converted to fp32 for all upper levels. Tokens staged with
//   +1 shift so leaf/mid token groups load as aligned int4/int2.
// ---------------------------------------------------------------------------
__device__ __forceinline__ float2 f2add(float2 a, float2 b) {
    return make_float2(a.x + b.x, a.y + b.y);
}
__device__ __forceinline__ float2 f2max(float2 a, float2 b) {
    return make_float2(fmaxf(a.x, b.x), fmaxf(a.y, b.y));
}
__device__ __forceinline__ __half2 asH2(uint32_t u) { return *(__half2*)&u; }
__device__ __forceinline__ float2 ldPf(const uint32_t* p) {
    uint32_t u = __ldg(p);
    return __half22float2(asH2(u));
}

__global__ void __launch_bounds__(512) tree_kernel(const int* __restrict__ tokens,
                                                   float* __restrict__ out) {
    __shared__ __align__(16) int stok[1024];   // token i at stok[i+1] (alignment shift)
    __shared__ float2 bufA[64 * 32];           // 16 KB
    __shared__ float2 bufB[32 * 32];           //  8 KB

    const int bh   = blockIdx.x;
    const int b    = bh >> 1;
    const int chb  = (bh & 1) << 6;
    const int tid  = threadIdx.x;
    const int lane = tid & 31;
    const int grp  = tid >> 5;           // 0..15
    const int* tokrow = tokens + (size_t)b * NNODES;

    for (int i = tid; i < NNODES; i += 512) stok[i + 1] = tokrow[i];
    __syncthreads();

    // node t -> Pc[t*64]; each uint32 = half2 = 2 channels
    const uint32_t* Pc = (const uint32_t*)g_Ph + (chb >> 1) + lane;
    float2 maxv = make_float2(-3.4e38f, -3.4e38f);
    __half2 hmax = __float2half2_rn(-65504.f);

    // fused levels 9..6: 64 subtrees rooted at level-6 nodes q = 63+m
    #pragma unroll
    for (int mi = 0; mi < 4; mi++) {
        int m = grp + mi * 16;
        int q = 63 + m;
        // aligned vector token loads (shift +1: 8q+8 and 4q+4 are 16B-aligned)
        int  tq  = stok[q + 1];
        int2 t2  = *(const int2*)&stok[2 * q + 2];
        int4 t4v = *(const int4*)&stok[4 * q + 4];
        int4 t8a = *(const int4*)&stok[8 * q + 8];
        int4 t8b = *(const int4*)&stok[8 * q + 12];

        uint32_t uq, u2[2], u4[4], u8[8];
        uq    = __ldg(Pc + (size_t)tq * 64);
        u2[0] = __ldg(Pc + (size_t)t2.x * 64);
        u2[1] = __ldg(Pc + (size_t)t2.y * 64);
        u4[0] = __ldg(Pc + (size_t)t4v.x * 64);
        u4[1] = __ldg(Pc + (size_t)t4v.y * 64);
        u4[2] = __ldg(Pc + (size_t)t4v.z * 64);
        u4[3] = __ldg(Pc + (size_t)t4v.w * 64);
        u8[0] = __ldg(Pc + (size_t)t8a.x * 64);
        u8[1] = __ldg(Pc + (size_t)t8a.y * 64);
        u8[2] = __ldg(Pc + (size_t)t8a.z * 64);
        u8[3] = __ldg(Pc + (size_t)t8a.w * 64);
        u8[4] = __ldg(Pc + (size_t)t8b.x * 64);
        u8[5] = __ldg(Pc + (size_t)t8b.y * 64);
        u8[6] = __ldg(Pc + (size_t)t8b.z * 64);
        u8[7] = __ldg(Pc + (size_t)t8b.w * 64);

        // leaf max (exact fp16 compares)
        __half2 lm01 = __hmax2(asH2(u8[0]), asH2(u8[1]));
        __half2 lm23 = __hmax2(asH2(u8[2]), asH2(u8[3]));
        __half2 lm45 = __hmax2(asH2(u8[4]), asH2(u8[5]));
        __half2 lm67 = __hmax2(asH2(u8[6]), asH2(u8[7]));
        hmax = __hmax2(hmax, __hmax2(__hmax2(lm01, lm23), __hmax2(lm45, lm67)));

        // level-8 sums in fp16 (2 HADD2 each; values ~0.035 -> err ~3e-5)
        __half2 s8h[4];
        #pragma unroll
        for (int j = 0; j < 4; j++) {
            s8h[j] = __hadd2(asH2(u4[j]), __hadd2(asH2(u8[2 * j]), asH2(u8[2 * j + 1])));
            hmax = __hmax2(hmax, s8h[j]);
        }

        // upper part of subtree in fp32
        float2 f80 = __half22float2(s8h[0]);
        float2 f81 = __half22float2(s8h[1]);
        float2 f82 = __half22float2(s8h[2]);
        float2 f83 = __half22float2(s8h[3]);
        float2 s70 = f2add(__half22float2(asH2(u2[0])), f2add(f80, f81));
        float2 s71 = f2add(__half22float2(asH2(u2[1])), f2add(f82, f83));
        maxv = f2max(maxv, f2max(s70, s71));
        float2 s6 = f2add(__half22float2(asH2(uq)), f2add(s70, s71));
        maxv = f2max(maxv, s6);
        bufA[m * 32 + lane] = s6;
    }
    // fold fp16 running max into fp32 max
    maxv = f2max(maxv, __half22float2(hmax));
    __syncthreads();

    #pragma unroll
    for (int ii = 0; ii < 2; ii++) {             // l5: A(64)->B(32)
        int i = grp + ii * 16;
        float2 v = f2add(f2add(bufA[(2 * i) * 32 + lane], bufA[(2 * i + 1) * 32 + lane]),
                         ldPf(Pc + (size_t)stok[32 + i] * 64));
        maxv = f2max(maxv, v);
        bufB[i * 32 + lane] = v;
    }
    __syncthreads();
    {                                            // l4: B(32)->A(16)
        int i = grp;
        float2 v = f2add(f2add(bufB[(2 * i) * 32 + lane], bufB[(2 * i + 1) * 32 + lane]),
                         ldPf(Pc + (size_t)stok[16 + i] * 64));
        maxv = f2max(maxv, v);
        bufA[i * 32 + lane] = v;
    }
    __syncthreads();
    if (grp < 8) {                               // l3: A(16)->B(8)
        int i = grp;
        float2 v = f2add(f2add(bufA[(2 * i) * 32 + lane], bufA[(2 * i + 1) * 32 + lane]),
                         ldPf(Pc + (size_t)stok[8 + i] * 64));
        maxv = f2max(maxv, v);
        bufB[i * 32 + lane] = v;
    }
    __syncthreads();
    if (grp < 4) {                               // l2: B(8)->A(4)
        int i = grp;
        float2 v = f2add(f2add(bufB[(2 * i) * 32 + lane], bufB[(2 * i + 1) * 32 + lane]),
                         ldPf(Pc + (size_t)stok[4 + i] * 64));
        maxv = f2max(maxv, v);
        bufA[i * 32 + lane] = v;
    }
    __syncthreads();
    if (grp < 2) {                               // l1: A(4)->B(2)
        int i = grp;
        float2 v = f2add(f2add(bufA[(2 * i) * 32 + lane], bufA[(2 * i + 1) * 32 + lane]),
                         ldPf(Pc + (size_t)stok[2 + i] * 64));
        maxv = f2max(maxv, v);
        bufB[i * 32 + lane] = v;
    }
    __syncthreads();
    if (grp == 0) {                              // l0: root
        float2 v = f2add(f2add(bufB[lane], bufB[32 + lane]),
                         ldPf(Pc + (size_t)stok[1] * 64));
        maxv = f2max(maxv, v);
    }

    // cross-group max (reuse bufA: [grp][lane])
    bufA[grp * 32 + lane] = maxv;
    __syncthreads();
    if (grp == 0) {
        float2 m = bufA[lane];
        #pragma unroll
        for (int g = 1; g < 16; g++) m = f2max(m, bufA[g * 32 + lane]);
        *(float2*)(out + (size_t)b * 128 + chb + 2 * lane) = m;
    }
}

// ---------------------------------------------------------------------------
// kernel_launch
// ---------------------------------------------------------------------------
extern "C" void kernel_launch(void* const* d_in, const int* in_sizes, int n_in,
                              void* d_out, int out_size) {
    const int*   tokens = (const int*)d_in[0];
    const float* emb    = (const float*)d_in[1];
    const float* Wc     = (const float*)d_in[2];
    const float* bc     = (const float*)d_in[3];
    float*       out    = (float*)d_out;

    const int smemA = 17408 + 34816;   // 52224 B -> 4 CTAs/SM
    cudaFuncSetAttribute(pmat_kernel, cudaFuncAttributeMaxDynamicSharedMemorySize, smemA);

    const int gridA = (VOCAB + MT - 1) / MT;   // 469
    pmat_kernel<<<gridA, 256, smemA>>>(emb, Wc, bc);
    tree_kernel<<<BS * 2, 512>>>(tokens, out);
}

// round 11
// speedup vs baseline: 4.9167x; 1.0097x over previous
#include <cuda_runtime.h>
#include <cuda_fp16.h>
#include <cstdint>

#define VOCAB 30000
#define EMB 128
#define ENC 128
#define BS 256
#define NNODES 1023

// Precomputed P[t][o] = dot(emb[t,:], W_c[o,:]) + b_c[o], stored fp16 (7.7 MB).
__device__ __half g_Ph[VOCAB * ENC];

// ---------------------------------------------------------------------------
// Kernel A: P = emb @ W_c^T + b_c via mma.sync m16n8k16 fp16 (HMMA, fp32 acc).
//   (unchanged: 469 CTAs x 256 thr, 52 KB smem, 4 CTA/SM, one wave)
// ---------------------------------------------------------------------------
#define MT 64
#define SAS 136   // smem row stride in fp16 elements (272 B: ldmatrix conflict-free)

#define MMA16816(c, a, b)                                                   \
    asm("mma.sync.aligned.m16n8k16.row.col.f32.f16.f16.f32 "                \
        "{%0,%1,%2,%3}, {%4,%5,%6,%7}, {%8,%9}, {%0,%1,%2,%3};"             \
        : "+f"((c)[0]), "+f"((c)[1]), "+f"((c)[2]), "+f"((c)[3])            \
        : "r"((a)[0]), "r"((a)[1]), "r"((a)[2]), "r"((a)[3]),               \
          "r"((b)[0]), "r"((b)[1]))

#define LDMX4(r, addr)                                                      \
    asm volatile("ldmatrix.sync.aligned.m8n8.x4.shared.b16 "                \
                 "{%0,%1,%2,%3}, [%4];"                                     \
                 : "=r"((r)[0]), "=r"((r)[1]), "=r"((r)[2]), "=r"((r)[3])   \
                 : "r"(addr))

__device__ __forceinline__ uint32_t su32(const void* p) {
    return (uint32_t)__cvta_generic_to_shared(p);
}

__device__ __forceinline__ void cvt_store(uint16_t* __restrict__ dst, int off, float4 x) {
    __half2 p01 = __floats2half2_rn(x.x, x.y);
    __half2 p23 = __floats2half2_rn(x.z, x.w);
    *(uint2*)(dst + off) = make_uint2(*(uint32_t*)&p01, *(uint32_t*)&p23);
}

__global__ void __launch_bounds__(256) pmat_kernel(const float* __restrict__ emb,
                                                   const float* __restrict__ Wc,
                                                   const float* __restrict__ bc) {
    extern __shared__ __align__(16) char dsm[];
    uint16_t* sA = (uint16_t*)dsm;                     // 64*136*2  = 17408 B
    uint16_t* sB = (uint16_t*)(dsm + 17408);           // 128*136*2 = 34816 B
    __shared__ float s_bias[128];

    const int tid = threadIdx.x;
    const int row0 = blockIdx.x * MT;

    if (tid < 128) s_bias[tid] = bc[tid];

    #pragma unroll 2
    for (int i = tid; i < MT * 32; i += 256) {
        int r = i >> 5, q = (i & 31) * 4;
        float4 x = make_float4(0.f, 0.f, 0.f, 0.f);
        if (row0 + r < VOCAB) x = *(const float4*)(emb + (size_t)(row0 + r) * 128 + q);
        cvt_store(sA, r * SAS + q, x);
    }
    #pragma unroll 4
    for (int i = tid; i < 128 * 32; i += 256) {
        int r = i >> 5, q = (i & 31) * 4;
        float4 w = *(const float4*)(Wc + (size_t)r * 128 + q);
        cvt_store(sB, r * SAS + q, w);
    }
    __syncthreads();

    const int warp = tid >> 5, lane = tid & 31;
    const int grp = lane >> 2, t4 = lane & 3;
    const int quad = lane >> 3, r8 = lane & 7;
    const int m0 = (warp & 1) * 32;
    const int n0 = (warp >> 1) * 32;

    uint32_t aA[2];
    #pragma unroll
    for (int mt = 0; mt < 2; mt++) {
        int rowA = m0 + mt * 16 + (quad & 1) * 8 + r8;
        int kA = (quad >> 1) * 8;
        aA[mt] = su32(sA) + (rowA * SAS + kA) * 2;
    }
    uint32_t aB[2];
    #pragma unroll
    for (int i = 0; i < 2; i++) {
        int rowB = n0 + i * 16 + (quad >> 1) * 8 + r8;
        int kB = (quad & 1) * 8;
        aB[i] = su32(sB) + (rowB * SAS + kB) * 2;
    }

    float acc[2][4][4];
    #pragma unroll
    for (int mt = 0; mt < 2; mt++)
        #pragma unroll
        for (int nt = 0; nt < 4; nt++)
            #pragma unroll
            for (int j = 0; j < 4; j++) acc[mt][nt][j] = 0.f;

    #pragma unroll
    for (int ks = 0; ks < 8; ks++) {
        const uint32_t off = ks * 32;
        uint32_t a[2][4];
        LDMX4(a[0], aA[0] + off);
        LDMX4(a[1], aA[1] + off);
        uint32_t bp[2][4];
        LDMX4(bp[0], aB[0] + off);
        LDMX4(bp[1], aB[1] + off);
        #pragma unroll
        for (int mt = 0; mt < 2; mt++)
            #pragma unroll
            for (int nt = 0; nt < 4; nt++) {
                uint32_t* bb = &bp[nt >> 1][(nt & 1) * 2];
                MMA16816(acc[mt][nt], a[mt], bb);
            }
    }

    #pragma unroll
    for (int mt = 0; mt < 2; mt++) {
        #pragma unroll
        for (int nt = 0; nt < 4; nt++) {
            int col = n0 + nt * 8 + t4 * 2;
            float b0 = s_bias[col], b1 = s_bias[col + 1];
            int r_lo = row0 + m0 + mt * 16 + grp;
            if (r_lo < VOCAB) {
                __half2 v = __floats2half2_rn(acc[mt][nt][0] + b0, acc[mt][nt][1] + b1);
                *(__half2*)(g_Ph + (size_t)r_lo * 128 + col) = v;
            }
            int r_hi = r_lo + 8;
            if (r_hi < VOCAB) {
                __half2 v = __floats2half2_rn(acc[mt][nt][2] + b0, acc[mt][nt][3] + b1);
                *(__half2*)(g_Ph + (size_t)r_hi * 128 + col) = v;
            }
        }
    }
}

// ---------------------------------------------------------------------------
// Kernel B: per (batch, channel-half) CTA: bottom-up subtree sums + max.
//   Levels 9+8 in fp16; upper-level P gathers PREFETCHED right after token
//   staging so the barrier-separated tail has no exposed L2 latency.
//   __launch_bounds__(512,3): ~42 regs lets the compiler keep prefetches +
//   gather batches in flight.
// ---------------------------------------------------------------------------
__device__ __forceinline__ float2 f2add(float2 a, float2 b) {
    return make_float2(a.x + b.x, a.y + b.y);
}
__device__ __forceinline__ float2 f2max(float2 a, float2 b) {
    return make_float2(fmaxf(a.x, b.x), fmaxf(a.y, b.y));
}
__device__ __forceinline__ __half2 asH2(uint32_t u) { return *(__half2*)&u; }
__device__ __forceinline__ float2 h2f(uint32_t u) { return __half22float2(asH2(u)); }

__global__ void __launch_bounds__(512, 3) tree_kernel(const int* __restrict__ tokens,
                                                      float* __restrict__ out) {
    __shared__ __align__(16) int stok[1024];   // token i at stok[i+1] (alignment shift)
    __shared__ float2 bufA[64 * 32];           // 16 KB
    __shared__ float2 bufB[32 * 32];           //  8 KB

    const int bh   = blockIdx.x;
    const int b    = bh >> 1;
    const int chb  = (bh & 1) << 6;
    const int tid  = threadIdx.x;
    const int lane = tid & 31;
    const int grp  = tid >> 5;           // 0..15
    const int* tokrow = tokens + (size_t)b * NNODES;

    for (int i = tid; i < NNODES; i += 512) stok[i + 1] = tokrow[i];
    __syncthreads();

    // node t -> Pc[t*64]; each uint32 = half2 = 2 channels
    const uint32_t* Pc = (const uint32_t*)g_Ph + (chb >> 1) + lane;

    // ---- prefetch upper-level (5..0) P gathers: in flight during fused loop
    uint32_t pu5a = __ldg(Pc + (size_t)stok[32 + grp] * 64);        // l5, i=grp
    uint32_t pu5b = __ldg(Pc + (size_t)stok[48 + grp] * 64);        // l5, i=grp+16
    uint32_t pu4  = __ldg(Pc + (size_t)stok[16 + grp] * 64);        // l4, i=grp
    uint32_t pu3 = 0, pu2 = 0, pu1 = 0, pu0 = 0;
    if (grp < 8)  pu3 = __ldg(Pc + (size_t)stok[8 + grp] * 64);
    if (grp < 4)  pu2 = __ldg(Pc + (size_t)stok[4 + grp] * 64);
    if (grp < 2)  pu1 = __ldg(Pc + (size_t)stok[2 + grp] * 64);
    if (grp == 0) pu0 = __ldg(Pc + (size_t)stok[1] * 64);

    float2 maxv = make_float2(-3.4e38f, -3.4e38f);
    __half2 hmax = __float2half2_rn(-65504.f);

    // fused levels 9..6: 64 subtrees rooted at level-6 nodes q = 63+m
    #pragma unroll
    for (int mi = 0; mi < 4; mi++) {
        int m = grp + mi * 16;
        int q = 63 + m;
        int  tq  = stok[q + 1];
        int2 t2  = *(const int2*)&stok[2 * q + 2];
        int4 t4v = *(const int4*)&stok[4 * q + 4];
        int4 t8a = *(const int4*)&stok[8 * q + 8];
        int4 t8b = *(const int4*)&stok[8 * q + 12];

        uint32_t uq, u2[2], u4[4], u8[8];
        uq    = __ldg(Pc + (size_t)tq * 64);
        u2[0] = __ldg(Pc + (size_t)t2.x * 64);
        u2[1] = __ldg(Pc + (size_t)t2.y * 64);
        u4[0] = __ldg(Pc + (size_t)t4v.x * 64);
        u4[1] = __ldg(Pc + (size_t)t4v.y * 64);
        u4[2] = __ldg(Pc + (size_t)t4v.z * 64);
        u4[3] = __ldg(Pc + (size_t)t4v.w * 64);
        u8[0] = __ldg(Pc + (size_t)t8a.x * 64);
        u8[1] = __ldg(Pc + (size_t)t8a.y * 64);
        u8[2] = __ldg(Pc + (size_t)t8a.z * 64);
        u8[3] = __ldg(Pc + (size_t)t8a.w * 64);
        u8[4] = __ldg(Pc + (size_t)t8b.x * 64);
        u8[5] = __ldg(Pc + (size_t)t8b.y * 64);
        u8[6] = __ldg(Pc + (size_t)t8b.z * 64);
        u8[7] = __ldg(Pc + (size_t)t8b.w * 64);

        // leaf max (exact fp16 compares)
        __half2 lm01 = __hmax2(asH2(u8[0]), asH2(u8[1]));
        __half2 lm23 = __hmax2(asH2(u8[2]), asH2(u8[3]));
        __half2 lm45 = __hmax2(asH2(u8[4]), asH2(u8[5]));
        __half2 lm67 = __hmax2(asH2(u8[6]), asH2(u8[7]));
        hmax = __hmax2(hmax, __hmax2(__hmax2(lm01, lm23), __hmax2(lm45, lm67)));

        // level-8 sums in fp16
        __half2 s8h[4];
        #pragma unroll
        for (int j = 0; j < 4; j++) {
            s8h[j] = __hadd2(asH2(u4[j]), __hadd2(asH2(u8[2 * j]), asH2(u8[2 * j + 1])));
            hmax = __hmax2(hmax, s8h[j]);
        }

        // upper part of subtree in fp32
        float2 f80 = __half22float2(s8h[0]);
        float2 f81 = __half22float2(s8h[1]);
        float2 f82 = __half22float2(s8h[2]);
        float2 f83 = __half22float2(s8h[3]);
        float2 s70 = f2add(h2f(u2[0]), f2add(f80, f81));
        float2 s71 = f2add(h2f(u2[1]), f2add(f82, f83));
        maxv = f2max(maxv, f2max(s70, s71));
        float2 s6 = f2add(h2f(uq), f2add(s70, s71));
        maxv = f2max(maxv, s6);
        bufA[m * 32 + lane] = s6;
    }
    maxv = f2max(maxv, __half22float2(hmax));
    __syncthreads();

    {                                            // l5: A(64)->B(32), i = grp, grp+16
        int i = grp;
        float2 v = f2add(f2add(bufA[(2 * i) * 32 + lane], bufA[(2 * i + 1) * 32 + lane]),
                         h2f(pu5a));
        maxv = f2max(maxv, v);
        bufB[i * 32 + lane] = v;
        i = grp + 16;
        float2 w = f2add(f2add(bufA[(2 * i) * 32 + lane], bufA[(2 * i + 1) * 32 + lane]),
                         h2f(pu5b));
        maxv = f2max(maxv, w);
        bufB[i * 32 + lane] = w;
    }
    __syncthreads();
    {                                            // l4: B(32)->A(16)
        int i = grp;
        float2 v = f2add(f2add(bufB[(2 * i) * 32 + lane], bufB[(2 * i + 1) * 32 + lane]),
                         h2f(pu4));
        maxv = f2max(maxv, v);
        bufA[i * 32 + lane] = v;
    }
    __syncthreads();
    if (grp < 8) {                               // l3: A(16)->B(8)
        int i = grp;
        float2 v = f2add(f2add(bufA[(2 * i) * 32 + lane], bufA[(2 * i + 1) * 32 + lane]),
                         h2f(pu3));
        maxv = f2max(maxv, v);
        bufB[i * 32 + lane] = v;
    }
    __syncthreads();
    if (grp < 4) {                               // l2: B(8)->A(4)
        int i = grp;
        float2 v = f2add(f2add(bufB[(2 * i) * 32 + lane], bufB[(2 * i + 1) * 32 + lane]),
                         h2f(pu2));
        maxv = f2max(maxv, v);
        bufA[i * 32 + lane] = v;
    }
    __syncthreads();
    if (grp < 2) {                               // l1: A(4)->B(2)
        int i = grp;
        float2 v = f2add(f2add(bufA[(2 * i) * 32 + lane], bufA[(2 * i + 1) * 32 + lane]),
                         h2f(pu1));
        maxv = f2max(maxv, v);
        bufB[i * 32 + lane] = v;
    }
    __syncthreads();
    if (grp == 0) {                              // l0: root
        float2 v = f2add(f2add(bufB[lane], bufB[32 + lane]), h2f(pu0));
        maxv = f2max(maxv, v);
    }

    // cross-group max (reuse bufA: [grp][lane])
    bufA[grp * 32 + lane] = maxv;
    __syncthreads();
    if (grp == 0) {
        float2 m = bufA[lane];
        #pragma unroll
        for (int g = 1; g < 16; g++) m = f2max(m, bufA[g * 32 + lane]);
        *(float2*)(out + (size_t)b * 128 + chb + 2 * lane) = m;
    }
}

// ---------------------------------------------------------------------------
// kernel_launch
// ---------------------------------------------------------------------------
extern "C" void kernel_launch(void* const* d_in, const int* in_sizes, int n_in,
                              void* d_out, int out_size) {
    const int*   tokens = (const int*)d_in[0];
    const float* emb    = (const float*)d_in[1];
    const float* Wc     = (const float*)d_in[2];
    const float* bc     = (const float*)d_in[3];
    float*       out    = (float*)d_out;

    const int smemA = 17408 + 34816;   // 52224 B -> 4 CTAs/SM
    cudaFuncSetAttribute(pmat_kernel, cudaFuncAttributeMaxDynamicSharedMemorySize, smemA);

    const int gridA = (VOCAB + MT - 1) / MT;   // 469
    pmat_kernel<<<gridA, 256, smemA>>>(emb, Wc, bc);
    tree_kernel<<<BS * 2, 512>>>(tokens, out);
}